// round 2
// baseline (speedup 1.0000x reference)
#include <cuda_runtime.h>
#include <cuda_bf16.h>

#define T_STEPS 30
#define BATCH   16384
#define HID     100
#define NP      7
#define BB      64          // batch rows per block
#define NTHREADS 800        // 8 (batch groups) x 100 (hidden units)
#define NB      8           // batch rows per thread

// ---- scratch (device globals: allocation-free) ----
__device__ float g_v1[4 * HID];           // Wih1 @ W1
__device__ float g_u1[4 * HID];           // Wih1 @ b1 + bih1 + bhh1
__device__ float g_in2[BATCH * 4 * HID];  // last @ Wih2^T + bih2 + bhh2

__device__ __forceinline__ float sigf(float x) {
    float e = __expf(-x);
    return __fdividef(1.0f, 1.0f + e);
}
__device__ __forceinline__ float tanhf_(float x) {
    float e = __expf(-2.0f * x);
    return __fdividef(1.0f - e, 1.0f + e);
}

// ---- tiny precompute: v1/u1 (runs once per launch, trivial cost) ----
__global__ void precompute_kernel(const float* __restrict__ W1,
                                  const float* __restrict__ b1,
                                  const float* __restrict__ Wih1,
                                  const float* __restrict__ bih1,
                                  const float* __restrict__ bhh1) {
    int j = blockIdx.x * blockDim.x + threadIdx.x;
    if (j < 4 * HID) {
        float v = 0.f, u = 0.f;
        for (int k = 0; k < HID; k++) {
            float w = Wih1[j * HID + k];
            v += w * W1[k];
            u += w * b1[k];
        }
        g_v1[j] = v;
        g_u1[j] = u + bih1[j] + bhh1[j];
    }
}

// GEMM micro-tile: acc[g][i] += sum_k h[brow+i][k] * W[g*100+tk][k]
// W_sm rows padded to 101 floats -> lane bank stride 5 (conflict-free),
// h reads are warp-broadcast (lanes share tb).
__device__ __forceinline__ void gemm100(float acc[4][NB],
                                        const float* __restrict__ W_sm,
                                        const float* __restrict__ h_sm,
                                        int tk, int brow) {
    const float* w0 = W_sm + tk * 101;
    const float* w1 = w0 + 100 * 101;
    const float* w2 = w1 + 100 * 101;
    const float* w3 = w2 + 100 * 101;
    const float* hp = h_sm + brow * HID;
#pragma unroll 4
    for (int k = 0; k < HID; k++) {
        float wv0 = w0[k], wv1 = w1[k], wv2 = w2[k], wv3 = w3[k];
#pragma unroll
        for (int i = 0; i < NB; i++) {
            float hv = hp[i * HID + k];
            acc[0][i] += wv0 * hv;
            acc[1][i] += wv1 * hv;
            acc[2][i] += wv2 * hv;
            acc[3][i] += wv3 * hv;
        }
    }
}

// smem layout (floats):
//   W_sm  [0,       40400)   weights padded 400 x 101
//   h_sm  [40400,   46800)   64 x 100 hidden state
//   x_sm  [46800,   48720)   30 x 64 input scalars
//   W2_sm [48720,   53620)   7 x 700 FC2 weights
#define SMEM_FLOATS 53620

__global__ __launch_bounds__(NTHREADS, 1)
void lstm_main_kernel(const float* __restrict__ x,
                      const float* __restrict__ Whh1,
                      const float* __restrict__ Wih2,
                      const float* __restrict__ Whh2,
                      const float* __restrict__ bih2,
                      const float* __restrict__ bhh2,
                      const float* __restrict__ W2,
                      const float* __restrict__ b2,
                      float* __restrict__ out) {
    extern __shared__ float sm[];
    float* W_sm  = sm;
    float* h_sm  = sm + 40400;
    float* x_sm  = sm + 46800;
    float* W2_sm = sm + 48720;

    const int tid  = threadIdx.x;
    const int tk   = tid % HID;      // hidden unit owned by this thread
    const int tb   = tid / HID;      // batch group 0..7
    const int brow = tb * NB;
    const int b0   = blockIdx.x * BB;

    // ---- prologue: Whh1, x slice, zero h ----
    for (int idx = tid; idx < 4 * HID * HID; idx += NTHREADS) {
        int j = idx / HID, k = idx - j * HID;
        W_sm[j * 101 + k] = Whh1[idx];
    }
    for (int idx = tid; idx < T_STEPS * BB; idx += NTHREADS) {
        int t = idx >> 6, i = idx & 63;
        x_sm[idx] = x[t * BATCH + b0 + i];
    }
    for (int idx = tid; idx < BB * HID; idx += NTHREADS) h_sm[idx] = 0.f;

    float v1g[4], u1g[4];
#pragma unroll
    for (int g = 0; g < 4; g++) {
        v1g[g] = g_v1[g * HID + tk];
        u1g[g] = g_u1[g * HID + tk];
    }

    float c[NB];
#pragma unroll
    for (int i = 0; i < NB; i++) c[i] = 0.f;

    // FC2 accumulator: first 448 threads own one (batch,row=p) output cell
    float y_reg = 0.f;
    int yb = 0, yp = 0;
    if (tid < BB * NP) {
        yb = tid / NP;
        yp = tid - yb * NP;
        y_reg = b2[yp];
    }
    __syncthreads();

    // ================= layer 1: 30 recurrent steps =================
    for (int t = 0; t < T_STEPS; t++) {
        float acc[4][NB];
#pragma unroll
        for (int i = 0; i < NB; i++) {
            float xv = x_sm[t * BB + brow + i];
            acc[0][i] = u1g[0] + xv * v1g[0];
            acc[1][i] = u1g[1] + xv * v1g[1];
            acc[2][i] = u1g[2] + xv * v1g[2];
            acc[3][i] = u1g[3] + xv * v1g[3];
        }
        gemm100(acc, W_sm, h_sm, tk, brow);

        float hn[NB];
#pragma unroll
        for (int i = 0; i < NB; i++) {
            float ig = sigf(acc[0][i]);
            float fg = sigf(acc[1][i]);
            float gg = tanhf_(acc[2][i]);
            float og = sigf(acc[3][i]);
            c[i] = fg * c[i] + ig * gg;
            hn[i] = og * tanhf_(c[i]);
        }
        __syncthreads();   // all reads of h_sm done
#pragma unroll
        for (int i = 0; i < NB; i++) h_sm[(brow + i) * HID + tk] = hn[i];
        __syncthreads();   // new h visible
    }

    // ================= layer 2 input GEMM: in2 = last @ Wih2^T + u2 =================
    for (int idx = tid; idx < 4 * HID * HID; idx += NTHREADS) {
        int j = idx / HID, k = idx - j * HID;
        W_sm[j * 101 + k] = Wih2[idx];
    }
    for (int idx = tid; idx < NP * NP * HID; idx += NTHREADS) W2_sm[idx] = W2[idx];
    __syncthreads();
    {
        float acc[4][NB];
        float u2g[4];
#pragma unroll
        for (int g = 0; g < 4; g++)
            u2g[g] = bih2[g * HID + tk] + bhh2[g * HID + tk];
#pragma unroll
        for (int i = 0; i < NB; i++) {
            acc[0][i] = u2g[0]; acc[1][i] = u2g[1];
            acc[2][i] = u2g[2]; acc[3][i] = u2g[3];
        }
        gemm100(acc, W_sm, h_sm, tk, brow);   // h_sm == last
#pragma unroll
        for (int g = 0; g < 4; g++)
#pragma unroll
            for (int i = 0; i < NB; i++)
                g_in2[(b0 + brow + i) * (4 * HID) + g * HID + tk] = acc[g][i];
    }
    __syncthreads();
    for (int idx = tid; idx < 4 * HID * HID; idx += NTHREADS) {
        int j = idx / HID, k = idx - j * HID;
        W_sm[j * 101 + k] = Whh2[idx];
    }
    __syncthreads();

    // ================= layer 2: 7 recurrent steps + fused FC2 =================
    for (int p = 0; p < NP; p++) {
        float acc[4][NB];
#pragma unroll
        for (int g = 0; g < 4; g++)
#pragma unroll
            for (int i = 0; i < NB; i++)
                acc[g][i] = g_in2[(b0 + brow + i) * (4 * HID) + g * HID + tk];

        gemm100(acc, W_sm, h_sm, tk, brow);

        float hn[NB];
#pragma unroll
        for (int i = 0; i < NB; i++) {
            float ig = sigf(acc[0][i]);
            float fg = sigf(acc[1][i]);
            float gg = tanhf_(acc[2][i]);
            float og = sigf(acc[3][i]);
            c[i] = fg * c[i] + ig * gg;
            hn[i] = og * tanhf_(c[i]);
        }
        __syncthreads();
#pragma unroll
        for (int i = 0; i < NB; i++) h_sm[(brow + i) * HID + tk] = hn[i];
        __syncthreads();

        // FC2 partial: y[b][p_out] += sum_k h2[b][k] * W2[p_out][p*100+k]
        if (tid < BB * NP) {
            const float* w  = W2_sm + yp * (NP * HID) + p * HID;
            const float* hh = h_sm + yb * HID;
            float s = 0.f;
#pragma unroll 4
            for (int k = 0; k < HID; k++) s += hh[k] * w[k];
            y_reg += s;
        }
    }

    if (tid < BB * NP) out[(b0 + yb) * NP + yp] = sigf(y_reg);
}

extern "C" void kernel_launch(void* const* d_in, const int* in_sizes, int n_in,
                              void* d_out, int out_size) {
    const float* x    = (const float*)d_in[0];
    const float* W1   = (const float*)d_in[1];
    const float* b1   = (const float*)d_in[2];
    const float* Wih1 = (const float*)d_in[3];
    const float* Whh1 = (const float*)d_in[4];
    const float* bih1 = (const float*)d_in[5];
    const float* bhh1 = (const float*)d_in[6];
    const float* Wih2 = (const float*)d_in[7];
    const float* Whh2 = (const float*)d_in[8];
    const float* bih2 = (const float*)d_in[9];
    const float* bhh2 = (const float*)d_in[10];
    const float* W2   = (const float*)d_in[11];
    const float* b2   = (const float*)d_in[12];
    float* out = (float*)d_out;

    const size_t smem_bytes = SMEM_FLOATS * sizeof(float);   // 214,480 B
    cudaFuncSetAttribute(lstm_main_kernel,
                         cudaFuncAttributeMaxDynamicSharedMemorySize,
                         (int)smem_bytes);

    precompute_kernel<<<1, 512>>>(W1, b1, Wih1, bih1, bhh1);
    lstm_main_kernel<<<BATCH / BB, NTHREADS, smem_bytes>>>(
        x, Whh1, Wih2, Whh2, bih2, bhh2, W2, b2, out);
}

// round 3
// speedup vs baseline: 1.0468x; 1.0468x over previous
#include <cuda_runtime.h>
#include <cuda_bf16.h>

#define T_STEPS 30
#define BATCH   16384
#define HID     100
#define NP      7
#define BB      64          // batch rows per block
#define NTHREADS 800        // 8 batch groups x 100 hidden units
#define NB      8           // batch rows per thread
#define HSTRIDE 68          // h buffer row stride (k-major), mult of 4, even

typedef unsigned long long u64;

// ---- scratch (device globals: allocation-free) ----
__device__ float g_v1[4 * HID];                    // Wih1 @ W1
__device__ float g_u1[4 * HID];                    // Wih1 @ b1 + bih1 + bhh1
__device__ u64   g_in2[(BATCH / BB) * NTHREADS * 16]; // per-thread layer-2 input pre-acts

// ---- f32x2 packed helpers ----
__device__ __forceinline__ u64 ffma2(u64 a, u64 b, u64 c) {
    u64 d;
    asm("fma.rn.f32x2 %0, %1, %2, %3;" : "=l"(d) : "l"(a), "l"(b), "l"(c));
    return d;
}
__device__ __forceinline__ u64 dup2(float w) {
    u64 r; asm("mov.b64 %0, {%1, %1};" : "=l"(r) : "f"(w)); return r;
}
__device__ __forceinline__ u64 pk2(float a, float b) {
    u64 r; asm("mov.b64 %0, {%1, %2};" : "=l"(r) : "f"(a), "f"(b)); return r;
}
__device__ __forceinline__ float2 unpk(u64 v) {
    float2 f; asm("mov.b64 {%0, %1}, %2;" : "=f"(f.x), "=f"(f.y) : "l"(v)); return f;
}
__device__ __forceinline__ float tanha(float x) {
    float y; asm("tanh.approx.f32 %0, %1;" : "=f"(y) : "f"(x)); return y;
}
__device__ __forceinline__ float sigf(float x) {      // 1 MUFU + 2 FMA
    return fmaf(tanha(0.5f * x), 0.5f, 0.5f);
}

// ---- tiny precompute: v1/u1 ----
__global__ void precompute_kernel(const float* __restrict__ W1,
                                  const float* __restrict__ b1,
                                  const float* __restrict__ Wih1,
                                  const float* __restrict__ bih1,
                                  const float* __restrict__ bhh1) {
    int j = blockIdx.x * blockDim.x + threadIdx.x;
    if (j < 4 * HID) {
        float v = 0.f, u = 0.f;
        for (int k = 0; k < HID; k++) {
            float w = Wih1[j * HID + k];
            v += w * W1[k];
            u += w * b1[k];
        }
        g_v1[j] = v;
        g_u1[j] = u + bih1[j] + bhh1[j];
    }
}

// GEMM micro-tile (f32x2): acc[g][ip] (+)= W[g][tk][k] * h[k][2ip..2ip+1]
// W4 layout: W4[k*400 + tk*4 + g]  -> one LDS.128 per thread per k (warp: 512B contiguous)
// h  layout: hb[k*HSTRIDE + row]   -> row pairs load as LDS.64 (broadcast within tb group)
__device__ __forceinline__ void gemm2(u64 acc[4][4],
                                      const float* __restrict__ W4,
                                      const float* __restrict__ hb,
                                      int tk, int brow) {
    const float4* wp = (const float4*)(W4 + tk * 4);
    const double* hp = (const double*)(hb + brow);
#pragma unroll 2
    for (int k = 0; k < HID; k++) {
        float4 w = wp[k * 100];                 // k*400 floats
        u64 h0 = __double_as_longlong(hp[k * (HSTRIDE / 2) + 0]);
        u64 h1 = __double_as_longlong(hp[k * (HSTRIDE / 2) + 1]);
        u64 h2 = __double_as_longlong(hp[k * (HSTRIDE / 2) + 2]);
        u64 h3 = __double_as_longlong(hp[k * (HSTRIDE / 2) + 3]);
        u64 w0 = dup2(w.x), w1 = dup2(w.y), w2 = dup2(w.z), w3 = dup2(w.w);
        acc[0][0] = ffma2(h0, w0, acc[0][0]);
        acc[0][1] = ffma2(h1, w0, acc[0][1]);
        acc[0][2] = ffma2(h2, w0, acc[0][2]);
        acc[0][3] = ffma2(h3, w0, acc[0][3]);
        acc[1][0] = ffma2(h0, w1, acc[1][0]);
        acc[1][1] = ffma2(h1, w1, acc[1][1]);
        acc[1][2] = ffma2(h2, w1, acc[1][2]);
        acc[1][3] = ffma2(h3, w1, acc[1][3]);
        acc[2][0] = ffma2(h0, w2, acc[2][0]);
        acc[2][1] = ffma2(h1, w2, acc[2][1]);
        acc[2][2] = ffma2(h2, w2, acc[2][2]);
        acc[2][3] = ffma2(h3, w2, acc[2][3]);
        acc[3][0] = ffma2(h0, w3, acc[3][0]);
        acc[3][1] = ffma2(h1, w3, acc[3][1]);
        acc[3][2] = ffma2(h2, w3, acc[3][2]);
        acc[3][3] = ffma2(h3, w3, acc[3][3]);
    }
}

// transposed+interleaved weight load: W4[k*400 + tg*4 + g] = G[(g*100+tg)*100 + k]
// smem writes: consecutive idx -> consecutive addr -> conflict-free
__device__ __forceinline__ void load_W4(float* __restrict__ W4,
                                        const float* __restrict__ G, int tid) {
    for (int idx = tid; idx < 4 * HID * HID; idx += NTHREADS) {
        int k = idx / 400;
        int m = idx - k * 400;
        int tg = m >> 2, g = m & 3;
        W4[idx] = G[(g * HID + tg) * HID + k];
    }
}

// smem map (floats):
//   W4  [0,     40000)
//   hb0 [40000, 46800)
//   hb1 [46800, 53600)
//   x   [53600, 55520)
#define SMEM_FLOATS 55520

__global__ __launch_bounds__(NTHREADS, 1)
void lstm_main_kernel(const float* __restrict__ x,
                      const float* __restrict__ Whh1,
                      const float* __restrict__ Wih2,
                      const float* __restrict__ Whh2,
                      const float* __restrict__ bih2,
                      const float* __restrict__ bhh2,
                      const float* __restrict__ W2,
                      const float* __restrict__ b2,
                      float* __restrict__ out) {
    extern __shared__ float sm[];
    float* W4  = sm;
    float* hb[2];
    hb[0] = sm + 40000;
    hb[1] = sm + 46800;
    float* x_sm = sm + 53600;

    const int tid  = threadIdx.x;
    const int tk   = tid % HID;
    const int tb   = tid / HID;
    const int brow = tb * NB;
    const int b0   = blockIdx.x * BB;

    // ---- prologue ----
    load_W4(W4, Whh1, tid);
    for (int idx = tid; idx < T_STEPS * BB; idx += NTHREADS) {
        int t = idx >> 6, i = idx & 63;
        x_sm[idx] = x[t * BATCH + b0 + i];
    }
    for (int idx = tid; idx < HID * HSTRIDE; idx += NTHREADS) hb[0][idx] = 0.f;

    float v1g[4], u1g[4];
#pragma unroll
    for (int g = 0; g < 4; g++) {
        v1g[g] = g_v1[g * HID + tk];
        u1g[g] = g_u1[g * HID + tk];
    }

    float c[NB];
#pragma unroll
    for (int i = 0; i < NB; i++) c[i] = 0.f;

    float y_reg = 0.f;
    int yb = 0, yp = 0;
    if (tid < BB * NP) {
        yb = tid / NP;
        yp = tid - yb * NP;
        y_reg = b2[yp];
    }
    __syncthreads();

    // ================= layer 1: 30 steps, double-buffered h, 1 sync/step =====
    for (int t = 0; t < T_STEPS; t++) {
        const float* hrd = hb[t & 1];
        float*       hwr = hb[(t + 1) & 1];

        u64 acc[4][4];
#pragma unroll
        for (int ip = 0; ip < 4; ip++) {
            float xe = x_sm[t * BB + brow + 2 * ip];
            float xo = x_sm[t * BB + brow + 2 * ip + 1];
#pragma unroll
            for (int g = 0; g < 4; g++)
                acc[g][ip] = pk2(fmaf(xe, v1g[g], u1g[g]),
                                 fmaf(xo, v1g[g], u1g[g]));
        }
        gemm2(acc, W4, hrd, tk, brow);

        float hn[NB];
#pragma unroll
        for (int ip = 0; ip < 4; ip++) {
            float2 gi = unpk(acc[0][ip]);
            float2 gf = unpk(acc[1][ip]);
            float2 gg = unpk(acc[2][ip]);
            float2 go = unpk(acc[3][ip]);
            int r0 = 2 * ip, r1 = 2 * ip + 1;
            c[r0] = sigf(gf.x) * c[r0] + sigf(gi.x) * tanha(gg.x);
            c[r1] = sigf(gf.y) * c[r1] + sigf(gi.y) * tanha(gg.y);
            hn[r0] = sigf(go.x) * tanha(c[r0]);
            hn[r1] = sigf(go.y) * tanha(c[r1]);
        }
        // write new h (k-major): 8 consecutive floats -> 2 x float4
        float4* dst = (float4*)(hwr + tk * HSTRIDE + brow);
        dst[0] = make_float4(hn[0], hn[1], hn[2], hn[3]);
        dst[1] = make_float4(hn[4], hn[5], hn[6], hn[7]);
        __syncthreads();
    }
    // `last` = h after step 30, lives in hb[0] (T_STEPS even)

    // ================= layer-2 input pre-acts: in2 = last @ Wih2^T + u2 ======
    load_W4(W4, Wih2, tid);
    __syncthreads();
    {
        u64 acc[4][4];
#pragma unroll
        for (int g = 0; g < 4; g++) {
            float u2 = bih2[g * HID + tk] + bhh2[g * HID + tk];
            u64 u2p = dup2(u2);
#pragma unroll
            for (int ip = 0; ip < 4; ip++) acc[g][ip] = u2p;
        }
        gemm2(acc, W4, hb[0], tk, brow);
        u64* slot = g_in2 + (size_t)(blockIdx.x * NTHREADS + tid) * 16;
#pragma unroll
        for (int g = 0; g < 4; g++)
#pragma unroll
            for (int ip = 0; ip < 4; ip++) slot[g * 4 + ip] = acc[g][ip];
    }
    __syncthreads();
    load_W4(W4, Whh2, tid);
    __syncthreads();

    // ================= layer 2: 7 steps + fused FC2 ==========================
    const u64* slot = g_in2 + (size_t)(blockIdx.x * NTHREADS + tid) * 16;
    for (int p = 0; p < NP; p++) {
        const float* hrd = hb[p & 1];
        float*       hwr = hb[(p + 1) & 1];

        u64 acc[4][4];
#pragma unroll
        for (int g = 0; g < 4; g++)
#pragma unroll
            for (int ip = 0; ip < 4; ip++) acc[g][ip] = slot[g * 4 + ip];

        gemm2(acc, W4, hrd, tk, brow);

        float hn[NB];
#pragma unroll
        for (int ip = 0; ip < 4; ip++) {
            float2 gi = unpk(acc[0][ip]);
            float2 gf = unpk(acc[1][ip]);
            float2 gg = unpk(acc[2][ip]);
            float2 go = unpk(acc[3][ip]);
            int r0 = 2 * ip, r1 = 2 * ip + 1;
            c[r0] = sigf(gf.x) * c[r0] + sigf(gi.x) * tanha(gg.x);
            c[r1] = sigf(gf.y) * c[r1] + sigf(gi.y) * tanha(gg.y);
            hn[r0] = sigf(go.x) * tanha(c[r0]);
            hn[r1] = sigf(go.y) * tanha(c[r1]);
        }
        float4* dst = (float4*)(hwr + tk * HSTRIDE + brow);
        dst[0] = make_float4(hn[0], hn[1], hn[2], hn[3]);
        dst[1] = make_float4(hn[4], hn[5], hn[6], hn[7]);
        __syncthreads();

        // FC2 partial: y[b][yp] += sum_k h2[b][k] * W2[yp][p*100+k]
        if (tid < BB * NP) {
            const float* w  = W2 + yp * (NP * HID) + p * HID;   // L1/const-cached
            const float* hh = hwr + yb;                          // k-major, stride HSTRIDE
            float s = 0.f;
#pragma unroll 4
            for (int k = 0; k < HID; k++) s = fmaf(hh[k * HSTRIDE], w[k], s);
            y_reg += s;
        }
    }

    if (tid < BB * NP) out[(b0 + yb) * NP + yp] = sigf(y_reg);
}

extern "C" void kernel_launch(void* const* d_in, const int* in_sizes, int n_in,
                              void* d_out, int out_size) {
    const float* x    = (const float*)d_in[0];
    const float* W1   = (const float*)d_in[1];
    const float* b1   = (const float*)d_in[2];
    const float* Wih1 = (const float*)d_in[3];
    const float* Whh1 = (const float*)d_in[4];
    const float* bih1 = (const float*)d_in[5];
    const float* bhh1 = (const float*)d_in[6];
    const float* Wih2 = (const float*)d_in[7];
    const float* Whh2 = (const float*)d_in[8];
    const float* bih2 = (const float*)d_in[9];
    const float* bhh2 = (const float*)d_in[10];
    const float* W2   = (const float*)d_in[11];
    const float* b2   = (const float*)d_in[12];
    float* out = (float*)d_out;

    const size_t smem_bytes = SMEM_FLOATS * sizeof(float);   // 222,080 B
    cudaFuncSetAttribute(lstm_main_kernel,
                         cudaFuncAttributeMaxDynamicSharedMemorySize,
                         (int)smem_bytes);

    precompute_kernel<<<1, 512>>>(W1, b1, Wih1, bih1, bhh1);
    lstm_main_kernel<<<BATCH / BB, NTHREADS, smem_bytes>>>(
        x, Whh1, Wih2, Whh2, bih2, bhh2, W2, b2, out);
}

// round 6
// speedup vs baseline: 3.4279x; 3.2745x over previous
#include <cuda_runtime.h>
#include <cuda_bf16.h>
#include <cstdint>

#define T_STEPS 30
#define BATCH   16384
#define NP      7
#define MROWS   64
#define NTHREADS 256
#define NCTAS   (BATCH / MROWS)     // 256

#define BSTR    208                 // B row stride bytes (104 halves), conflict-free ldsm
#define ASTR    240                 // A(h) row stride bytes (120 halves), conflict-free ldsm

// smem byte offsets
#define SM_BH 0                     // B hi: 400 x 208 = 83200
#define SM_BL 83200                 // B lo: 83200
#define SM_AH 166400                // A hi: 64 x 240 = 15360
#define SM_AL 181760                // A lo: 15360
#define SM_W2 197120                // W2 staged: 4900 floats = 19600
#define SMEM_BYTES 216720

// ---- device scratch (allocation-free) ----
__device__ float  g_v1[400];                 // Wih1 @ W1
__device__ float  g_u1[400];                 // Wih1 @ b1 + bih1 + bhh1
__device__ float4 g_in2[(size_t)NCTAS * NTHREADS * 28];   // layer-2 input pre-acts (frag layout)

// ============================ helpers ============================
__device__ __forceinline__ uint32_t sptr(const void* p) {
    uint32_t a;
    asm("{ .reg .u64 t; cvta.to.shared.u64 t, %1; cvt.u32.u64 %0, t; }" : "=r"(a) : "l"(p));
    return a;
}
__device__ __forceinline__ float tanha(float x) {
    float y; asm("tanh.approx.f32 %0, %1;" : "=f"(y) : "f"(x)); return y;
}
__device__ __forceinline__ float sigf(float x) { return fmaf(tanha(0.5f * x), 0.5f, 0.5f); }

__device__ __forceinline__ void ldsm_x4(uint32_t* r, uint32_t a) {
    asm volatile("ldmatrix.sync.aligned.m8n8.x4.shared.b16 {%0,%1,%2,%3}, [%4];"
                 : "=r"(r[0]), "=r"(r[1]), "=r"(r[2]), "=r"(r[3]) : "r"(a));
}
__device__ __forceinline__ void ldsm_x2(uint32_t* r, uint32_t a) {
    asm volatile("ldmatrix.sync.aligned.m8n8.x2.shared.b16 {%0,%1}, [%2];"
                 : "=r"(r[0]), "=r"(r[1]) : "r"(a));
}
__device__ __forceinline__ void mma_bf16(float* d, const uint32_t* a, const uint32_t* b) {
    asm volatile("mma.sync.aligned.m16n8k16.row.col.f32.bf16.bf16.f32 "
                 "{%0,%1,%2,%3}, {%4,%5,%6,%7}, {%8,%9}, {%0,%1,%2,%3};"
                 : "+f"(d[0]), "+f"(d[1]), "+f"(d[2]), "+f"(d[3])
                 : "r"(a[0]), "r"(a[1]), "r"(a[2]), "r"(a[3]), "r"(b[0]), "r"(b[1]));
}
__device__ __forceinline__ void split_bf16(float v, uint16_t& hi, uint16_t& lo) {
    __nv_bfloat16 h = __float2bfloat16(v);
    hi = __bfloat16_as_ushort(h);
    lo = __bfloat16_as_ushort(__float2bfloat16(v - __bfloat162float(h)));
}

// ============================ precompute (tiny) ============================
__global__ void precompute_kernel(const float* __restrict__ W1,
                                  const float* __restrict__ b1,
                                  const float* __restrict__ Wih1,
                                  const float* __restrict__ bih1,
                                  const float* __restrict__ bhh1) {
    int j = blockIdx.x * blockDim.x + threadIdx.x;
    if (j < 400) {
        float v = 0.f, u = 0.f;
        for (int k = 0; k < 100; k++) {
            float w = Wih1[j * 100 + k];
            v += w * W1[k];
            u += w * b1[k];
        }
        g_v1[j] = v;
        g_u1[j] = u + bih1[j] + bhh1[j];
    }
}

// B fill: row n = 4*j + g <- source gate-row (g*100 + j).
// K cols: 0..99 weights, 100 = u1(+u2), 101 = v, 102..103 zero.
__device__ void fill_B(char* sm, const float* __restrict__ W,
                       const float* __restrict__ ua, const float* __restrict__ ub,
                       const float* __restrict__ v, int tid) {
    for (int idx = tid; idx < 400 * 104; idx += NTHREADS) {
        int n = idx / 104, k = idx - n * 104;
        int srow = (n & 3) * 100 + (n >> 2);
        float val = 0.f;
        if (k < 100)       val = W[srow * 100 + k];
        else if (k == 100) { if (ua) val = ua[srow]; if (ub) val += ub[srow]; }
        else if (k == 101) { if (v)  val = v[srow]; }
        uint16_t hi, lo; split_bf16(val, hi, lo);
        *(uint16_t*)(sm + SM_BH + n * BSTR + k * 2) = hi;
        *(uint16_t*)(sm + SM_BL + n * BSTR + k * 2) = lo;
    }
}

// 3-term split-bf16 GEMM. A = h tile (64 x 112), B slice = n8-tiles [start, start+count).
__device__ __forceinline__ void gemm_step(float acc[4][7][4],
                                          uint32_t aAH, uint32_t aAL,
                                          uint32_t aBH, uint32_t aBL,
                                          int start, int count) {
#pragma unroll
    for (int ch = 0; ch < 7; ch++) {
        uint32_t ah[4][4], al[4][4];
#pragma unroll
        for (int mt = 0; mt < 4; mt++) {
            ldsm_x4(ah[mt], aAH + mt * (16 * ASTR) + ch * 32);
            ldsm_x4(al[mt], aAL + mt * (16 * ASTR) + ch * 32);
        }
#pragma unroll
        for (int ti = 0; ti < 7; ti++) {
            if (ti < count) {
                uint32_t boff = (uint32_t)(start + ti) * (8 * BSTR) + ch * 32;
                uint32_t bh[2], bl[2];
                ldsm_x2(bh, aBH + boff);
                ldsm_x2(bl, aBL + boff);
#pragma unroll
                for (int mt = 0; mt < 4; mt++) {
                    mma_bf16(acc[mt][ti], ah[mt], bh);
                    mma_bf16(acc[mt][ti], al[mt], bh);
                    mma_bf16(acc[mt][ti], ah[mt], bl);
                }
            }
        }
    }
}

// ============================ main kernel ============================
__global__ __launch_bounds__(NTHREADS, 1)
void lstm_hmma_kernel(const float* __restrict__ x,
                      const float* __restrict__ Whh1,
                      const float* __restrict__ Wih2,
                      const float* __restrict__ Whh2,
                      const float* __restrict__ bih2,
                      const float* __restrict__ bhh2,
                      const float* __restrict__ W2,
                      const float* __restrict__ b2,
                      float* __restrict__ out) {
    extern __shared__ char sm[];
    const uint32_t smb = sptr(sm);
    const int tid  = threadIdx.x;
    const int warp = tid >> 5;
    const int lane = tid & 31;
    const int cq   = lane & 3;        // col quad
    const int rq   = lane >> 2;       // row within 8
    const bool even = (cq & 1) == 0;
    const int b0   = blockIdx.x * MROWS;

    // N-tile slice per warp: warps 0,1 -> 7 tiles; 2..7 -> 6 tiles
    const int start = warp * 6 + (warp < 2 ? warp : 2);
    const int count = 6 + (warp < 2 ? 1 : 0);

    // ldmatrix per-lane base addresses
    const uint32_t aAH = smb + SM_AH + (uint32_t)(lane & 15) * ASTR + ((lane >> 4) ? 16u : 0u);
    const uint32_t aAL = smb + SM_AL + (uint32_t)(lane & 15) * ASTR + ((lane >> 4) ? 16u : 0u);
    const uint32_t aBH = smb + SM_BH + (uint32_t)(lane & 7) * BSTR + (((lane >> 3) & 1) ? 16u : 0u);
    const uint32_t aBL = smb + SM_BL + (uint32_t)(lane & 7) * BSTR + (((lane >> 3) & 1) ? 16u : 0u);

    // ---- prologue: B=Whh1(+u1,v1), A(h)=0 with bias cols, W2 staged ----
    fill_B(sm, Whh1, g_u1, (const float*)nullptr, g_v1, tid);
    for (int i = tid; i < (MROWS * ASTR) / 4; i += NTHREADS) {   // zero both A planes (u32)
        *(uint32_t*)(sm + SM_AH + i * 4) = 0u;
        *(uint32_t*)(sm + SM_AL + i * 4) = 0u;
    }
    for (int i = tid; i < NP * 700; i += NTHREADS)
        *(float*)(sm + SM_W2 + i * 4) = W2[i];
    __syncthreads();
    if (tid < MROWS) {    // bias cols: col100 = 1.0, col101 = x[0]
        *(uint16_t*)(sm + SM_AH + tid * ASTR + 100 * 2) = 0x3F80u;
        uint16_t hi, lo; split_bf16(x[b0 + tid], hi, lo);
        *(uint16_t*)(sm + SM_AH + tid * ASTR + 101 * 2) = hi;
        *(uint16_t*)(sm + SM_AL + tid * ASTR + 101 * 2) = lo;
    }
    __syncthreads();

    float creg[4][7];
#pragma unroll
    for (int mt = 0; mt < 4; mt++)
#pragma unroll
        for (int ti = 0; ti < 7; ti++) creg[mt][ti] = 0.f;

    float y[NP];
#pragma unroll
    for (int q = 0; q < NP; q++) y[q] = 0.f;

    // ==================== layer 1: 30 steps ====================
#pragma unroll 1
    for (int t = 0; t < T_STEPS; t++) {
        float acc[4][7][4];
#pragma unroll
        for (int mt = 0; mt < 4; mt++)
#pragma unroll
            for (int ti = 0; ti < 7; ti++)
#pragma unroll
                for (int e = 0; e < 4; e++) acc[mt][ti][e] = 0.f;

        gemm_step(acc, aAH, aAL, aBH, aBL, start, count);
        __syncthreads();   // all ldsm reads of A complete before h writes

        // epilogue: gate exchange + cell math + h write
#pragma unroll
        for (int mt = 0; mt < 4; mt++)
#pragma unroll
            for (int ti = 0; ti < 7; ti++) {
                if (ti < count) {
                    float* d = acc[mt][ti];
                    float s0 = even ? d[2] : d[0];
                    float s1 = even ? d[3] : d[1];
                    float e0 = __shfl_xor_sync(0xffffffffu, s0, 1);
                    float e1 = __shfl_xor_sync(0xffffffffu, s1, 1);
                    float gi, gf, gg, go;
                    if (even) { gi = d[0]; gf = d[1]; gg = e0; go = e1; }
                    else      { gi = e0;  gf = e1;  gg = d[2]; go = d[3]; }
                    float cc = creg[mt][ti];
                    cc = sigf(gf) * cc + sigf(gi) * tanha(gg);
                    creg[mt][ti] = cc;
                    float h = sigf(go) * tanha(cc);
                    int row  = mt * 16 + rq + (even ? 0 : 8);
                    int unit = 2 * (start + ti) + (cq >> 1);
                    uint16_t hi, lo; split_bf16(h, hi, lo);
                    *(uint16_t*)(sm + SM_AH + row * ASTR + unit * 2) = hi;
                    *(uint16_t*)(sm + SM_AL + row * ASTR + unit * 2) = lo;
                }
            }
        if (tid < MROWS) {   // next x into col101
            float xv = (t < T_STEPS - 1) ? x[(t + 1) * BATCH + b0 + tid] : 0.f;
            uint16_t hi, lo; split_bf16(xv, hi, lo);
            *(uint16_t*)(sm + SM_AH + tid * ASTR + 101 * 2) = hi;
            *(uint16_t*)(sm + SM_AL + tid * ASTR + 101 * 2) = lo;
        }
        __syncthreads();
    }

    // ==================== layer-2 input GEMM (once) ====================
    fill_B(sm, Wih2, bih2, bhh2, (const float*)nullptr, tid);
    __syncthreads();
    {
        float acc[4][7][4];
#pragma unroll
        for (int mt = 0; mt < 4; mt++)
#pragma unroll
            for (int ti = 0; ti < 7; ti++)
#pragma unroll
                for (int e = 0; e < 4; e++) acc[mt][ti][e] = 0.f;
        gemm_step(acc, aAH, aAL, aBH, aBL, start, count);
        float4* slot = &g_in2[((size_t)blockIdx.x * NTHREADS + tid) * 28];
#pragma unroll
        for (int mt = 0; mt < 4; mt++)
#pragma unroll
            for (int ti = 0; ti < 7; ti++)
                if (ti < count)
                    slot[mt * 7 + ti] = make_float4(acc[mt][ti][0], acc[mt][ti][1],
                                                    acc[mt][ti][2], acc[mt][ti][3]);
    }
    __syncthreads();
    fill_B(sm, Whh2, (const float*)nullptr, (const float*)nullptr,
           (const float*)nullptr, tid);
    __syncthreads();

    // ==================== layer 2: 7 steps + fused FC2 ====================
    const float4* slot = &g_in2[((size_t)blockIdx.x * NTHREADS + tid) * 28];
#pragma unroll 1
    for (int ps = 0; ps < NP; ps++) {
        float acc[4][7][4];
#pragma unroll
        for (int mt = 0; mt < 4; mt++)
#pragma unroll
            for (int ti = 0; ti < 7; ti++) {
                float4 v = (ti < count) ? slot[mt * 7 + ti] : make_float4(0.f, 0.f, 0.f, 0.f);
                acc[mt][ti][0] = v.x; acc[mt][ti][1] = v.y;
                acc[mt][ti][2] = v.z; acc[mt][ti][3] = v.w;
            }

        gemm_step(acc, aAH, aAL, aBH, aBL, start, count);
        __syncthreads();

#pragma unroll
        for (int mt = 0; mt < 4; mt++)
#pragma unroll
            for (int ti = 0; ti < 7; ti++) {
                if (ti < count) {
                    float* d = acc[mt][ti];
                    float s0 = even ? d[2] : d[0];
                    float s1 = even ? d[3] : d[1];
                    float e0 = __shfl_xor_sync(0xffffffffu, s0, 1);
                    float e1 = __shfl_xor_sync(0xffffffffu, s1, 1);
                    float gi, gf, gg, go;
                    if (even) { gi = d[0]; gf = d[1]; gg = e0; go = e1; }
                    else      { gi = e0;  gf = e1;  gg = d[2]; go = d[3]; }
                    float cc = creg[mt][ti];
                    cc = sigf(gf) * cc + sigf(gi) * tanha(gg);
                    creg[mt][ti] = cc;
                    float h = sigf(go) * tanha(cc);
                    int row  = mt * 16 + rq + (even ? 0 : 8);
                    int unit = 2 * (start + ti) + (cq >> 1);
                    uint16_t hi, lo; split_bf16(h, hi, lo);
                    *(uint16_t*)(sm + SM_AH + row * ASTR + unit * 2) = hi;
                    *(uint16_t*)(sm + SM_AL + row * ASTR + unit * 2) = lo;
                }
            }
        __syncthreads();

        // FC2 partial: threads 0..127, row = tid/2, j-half = tid%2
        if (tid < 2 * MROWS) {
            int row = tid >> 1;
            int j0  = (tid & 1) * 50;
            const float* w2s = (const float*)(sm + SM_W2);
#pragma unroll 2
            for (int jj = 0; jj < 50; jj++) {
                int j = j0 + jj;
                float h = __bfloat162float(*(const __nv_bfloat16*)(sm + SM_AH + row * ASTR + j * 2)) +
                          __bfloat162float(*(const __nv_bfloat16*)(sm + SM_AL + row * ASTR + j * 2));
#pragma unroll
                for (int q = 0; q < NP; q++)
                    y[q] = fmaf(h, w2s[q * 700 + ps * 100 + j], y[q]);
            }
        }
    }

    // ==================== output ====================
    if (tid < 2 * MROWS) {
        int row = tid >> 1;
#pragma unroll
        for (int q = 0; q < NP; q++) {
            float v = y[q] + __shfl_xor_sync(0xffffffffu, y[q], 1);
            if ((tid & 1) == 0)
                out[(size_t)(b0 + row) * NP + q] = sigf(v + b2[q]);
        }
    }
}

// ============================ launch ============================
extern "C" void kernel_launch(void* const* d_in, const int* in_sizes, int n_in,
                              void* d_out, int out_size) {
    const float* x    = (const float*)d_in[0];
    const float* W1   = (const float*)d_in[1];
    const float* b1   = (const float*)d_in[2];
    const float* Wih1 = (const float*)d_in[3];
    const float* Whh1 = (const float*)d_in[4];
    const float* bih1 = (const float*)d_in[5];
    const float* bhh1 = (const float*)d_in[6];
    const float* Wih2 = (const float*)d_in[7];
    const float* Whh2 = (const float*)d_in[8];
    const float* bih2 = (const float*)d_in[9];
    const float* bhh2 = (const float*)d_in[10];
    const float* W2   = (const float*)d_in[11];
    const float* b2   = (const float*)d_in[12];
    float* out = (float*)d_out;

    cudaFuncSetAttribute(lstm_hmma_kernel,
                         cudaFuncAttributeMaxDynamicSharedMemorySize, SMEM_BYTES);

    precompute_kernel<<<1, 512>>>(W1, b1, Wih1, bih1, bhh1);
    lstm_hmma_kernel<<<NCTAS, NTHREADS, SMEM_BYTES>>>(
        x, Whh1, Wih2, Whh2, bih2, bhh2, W2, b2, out);
}

// round 7
// speedup vs baseline: 3.5942x; 1.0485x over previous
#include <cuda_runtime.h>
#include <cuda_bf16.h>
#include <cstdint>

#define T_STEPS 30
#define BATCH   16384
#define NP      7
#define MROWS   64
#define NTHREADS 256
#define NCTAS   (BATCH / MROWS)     // 256

#define BSTR    208                 // B row stride bytes (104 halves), conflict-free ldsm
#define ASTR    240                 // A(h) row stride bytes (120 halves), conflict-free ldsm

// smem byte offsets
#define SM_BH  0                    // B hi: 400 x 208 = 83200
#define SM_BL  83200                // B lo: 83200
#define SM_A   166400               // A planes: [AH0|AL0|AH1|AL1], each 64*240=15360
#define APLANE 15360
#define ABUF   30720                // one parity buffer (hi+lo)
#define SM_W2S 227840               // staged W2 slice for current ps: 700 floats
#define SMEM_BYTES 230640

// ---- device scratch (allocation-free) ----
__device__ float  g_v1[400];                 // Wih1 @ W1
__device__ float  g_u1[400];                 // Wih1 @ b1 + bih1 + bhh1
__device__ float4 g_in2[(size_t)NCTAS * NTHREADS * 28];   // layer-2 input pre-acts (frag layout)

// ============================ helpers ============================
__device__ __forceinline__ uint32_t sptr(const void* p) {
    uint32_t a;
    asm("{ .reg .u64 t; cvta.to.shared.u64 t, %1; cvt.u32.u64 %0, t; }" : "=r"(a) : "l"(p));
    return a;
}
__device__ __forceinline__ float tanha(float x) {
    float y; asm("tanh.approx.f32 %0, %1;" : "=f"(y) : "f"(x)); return y;
}
__device__ __forceinline__ float sigf(float x) { return fmaf(tanha(0.5f * x), 0.5f, 0.5f); }

__device__ __forceinline__ void ldsm_x4(uint32_t* r, uint32_t a) {
    asm volatile("ldmatrix.sync.aligned.m8n8.x4.shared.b16 {%0,%1,%2,%3}, [%4];"
                 : "=r"(r[0]), "=r"(r[1]), "=r"(r[2]), "=r"(r[3]) : "r"(a));
}
__device__ __forceinline__ void mma_bf16(float* d, const uint32_t* a, const uint32_t* b) {
    asm volatile("mma.sync.aligned.m16n8k16.row.col.f32.bf16.bf16.f32 "
                 "{%0,%1,%2,%3}, {%4,%5,%6,%7}, {%8,%9}, {%0,%1,%2,%3};"
                 : "+f"(d[0]), "+f"(d[1]), "+f"(d[2]), "+f"(d[3])
                 : "r"(a[0]), "r"(a[1]), "r"(a[2]), "r"(a[3]), "r"(b[0]), "r"(b[1]));
}
__device__ __forceinline__ void split_bf16(float v, uint16_t& hi, uint16_t& lo) {
    __nv_bfloat16 h = __float2bfloat16(v);
    hi = __bfloat16_as_ushort(h);
    lo = __bfloat16_as_ushort(__float2bfloat16(v - __bfloat162float(h)));
}

// ============================ precompute (tiny) ============================
__global__ void precompute_kernel(const float* __restrict__ W1,
                                  const float* __restrict__ b1,
                                  const float* __restrict__ Wih1,
                                  const float* __restrict__ bih1,
                                  const float* __restrict__ bhh1) {
    int j = blockIdx.x * blockDim.x + threadIdx.x;
    if (j < 400) {
        float v = 0.f, u = 0.f;
        for (int k = 0; k < 100; k++) {
            float w = Wih1[j * 100 + k];
            v += w * W1[k];
            u += w * b1[k];
        }
        g_v1[j] = v;
        g_u1[j] = u + bih1[j] + bhh1[j];
    }
}

// B fill: row n = 4*j + g <- source gate-row (g*100 + j).
// K cols: 0..99 weights, 100 = u1(+u2), 101 = v, 102..103 zero.
__device__ void fill_B(char* sm, const float* __restrict__ W,
                       const float* __restrict__ ua, const float* __restrict__ ub,
                       const float* __restrict__ v, int tid) {
    for (int idx = tid; idx < 400 * 104; idx += NTHREADS) {
        int n = idx / 104, k = idx - n * 104;
        int srow = (n & 3) * 100 + (n >> 2);
        float val = 0.f;
        if (k < 100)       val = W[srow * 100 + k];
        else if (k == 100) { if (ua) val = ua[srow]; if (ub) val += ub[srow]; }
        else if (k == 101) { if (v)  val = v[srow]; }
        uint16_t hi, lo; split_bf16(val, hi, lo);
        *(uint16_t*)(sm + SM_BH + n * BSTR + k * 2) = hi;
        *(uint16_t*)(sm + SM_BL + n * BSTR + k * 2) = lo;
    }
}

// 3-term split-bf16 GEMM, compile-time tile count (no ragged branches).
// B hi+lo fetched in ONE ldsm_x4 (lanes 0-15 hi plane, 16-31 lo plane).
template<int COUNT>
__device__ __forceinline__ void gemm_step(float acc[4][7][4],
                                          uint32_t aAH, uint32_t aAL,
                                          uint32_t aB, int start) {
#pragma unroll
    for (int ch = 0; ch < 7; ch++) {
        uint32_t ah[4][4], al[4][4];
#pragma unroll
        for (int mt = 0; mt < 4; mt++) {
            ldsm_x4(ah[mt], aAH + mt * (16 * ASTR) + ch * 32);
            ldsm_x4(al[mt], aAL + mt * (16 * ASTR) + ch * 32);
        }
#pragma unroll
        for (int ti = 0; ti < COUNT; ti++) {
            uint32_t b[4];   // b[0..1] = Bh frag, b[2..3] = Bl frag
            ldsm_x4(b, aB + (uint32_t)(start + ti) * (8 * BSTR) + ch * 32);
#pragma unroll
            for (int mt = 0; mt < 4; mt++) {
                mma_bf16(acc[mt][ti], ah[mt], b);       // hh * Bh
                mma_bf16(acc[mt][ti], al[mt], b);       // hl * Bh
                mma_bf16(acc[mt][ti], ah[mt], b + 2);   // hh * Bl
            }
        }
    }
}

// epilogue: gate exchange via shfl, LSTM cell math, h -> write buffer (bf16 hi/lo)
template<int COUNT>
__device__ __forceinline__ void lstm_epi(float acc[4][7][4], float creg[4][7],
                                         char* sm, uint32_t AHw, uint32_t ALw,
                                         int start, int lane) {
    const int cq = lane & 3;
    const int rq = lane >> 2;
    const bool even = (cq & 1) == 0;
#pragma unroll
    for (int mt = 0; mt < 4; mt++)
#pragma unroll
        for (int ti = 0; ti < COUNT; ti++) {
            float* d = acc[mt][ti];
            float s0 = even ? d[2] : d[0];
            float s1 = even ? d[3] : d[1];
            float e0 = __shfl_xor_sync(0xffffffffu, s0, 1);
            float e1 = __shfl_xor_sync(0xffffffffu, s1, 1);
            float gi, gf, gg, go;
            if (even) { gi = d[0]; gf = d[1]; gg = e0; go = e1; }
            else      { gi = e0;  gf = e1;  gg = d[2]; go = d[3]; }
            float cc = creg[mt][ti];
            cc = sigf(gf) * cc + sigf(gi) * tanha(gg);
            creg[mt][ti] = cc;
            float h = sigf(go) * tanha(cc);
            int row  = mt * 16 + rq + (even ? 0 : 8);
            int unit = 2 * (start + ti) + (cq >> 1);
            uint16_t hi, lo; split_bf16(h, hi, lo);
            *(uint16_t*)(sm + AHw + row * ASTR + unit * 2) = hi;
            *(uint16_t*)(sm + ALw + row * ASTR + unit * 2) = lo;
        }
}

// ============================ main kernel ============================
__global__ __launch_bounds__(NTHREADS, 1)
void lstm_hmma_kernel(const float* __restrict__ x,
                      const float* __restrict__ Whh1,
                      const float* __restrict__ Wih2,
                      const float* __restrict__ Whh2,
                      const float* __restrict__ bih2,
                      const float* __restrict__ bhh2,
                      const float* __restrict__ W2,
                      const float* __restrict__ b2,
                      float* __restrict__ out) {
    extern __shared__ char sm[];
    const uint32_t smb = sptr(sm);
    const int tid  = threadIdx.x;
    const int warp = tid >> 5;
    const int lane = tid & 31;
    const int b0   = blockIdx.x * MROWS;

    // warp n-slice: warps 0,1 -> 7 tiles; 2..7 -> 6 tiles (2*7 + 6*6 = 50)
    const int start = (warp < 2) ? warp * 7 : 14 + (warp - 2) * 6;
    const int count = (warp < 2) ? 7 : 6;

    // ldmatrix lane addresses
    const uint32_t aAH0 = smb + SM_A + (uint32_t)(lane & 15) * ASTR + ((lane >> 4) ? 16u : 0u);
    const uint32_t aAL0 = aAH0 + APLANE;
    const uint32_t aAH1 = aAH0 + ABUF;
    const uint32_t aAL1 = aAH1 + APLANE;
    const uint32_t aB   = smb + ((lane < 16) ? SM_BH : SM_BL)
                        + (uint32_t)(lane & 7) * BSTR + (((lane >> 3) & 1) ? 16u : 0u);

    // ---- prologue ----
    fill_B(sm, Whh1, g_u1, (const float*)nullptr, g_v1, tid);
    for (int i = tid; i < (2 * ABUF) / 4; i += NTHREADS)
        *(uint32_t*)(sm + SM_A + i * 4) = 0u;
    __syncthreads();
    if (tid < MROWS) {
        // col100 = 1.0 in both parity buffers; col101 = x[0] in buffer 0
        *(uint16_t*)(sm + SM_A + tid * ASTR + 200) = 0x3F80u;
        *(uint16_t*)(sm + SM_A + ABUF + tid * ASTR + 200) = 0x3F80u;
        uint16_t hi, lo; split_bf16(x[b0 + tid], hi, lo);
        *(uint16_t*)(sm + SM_A + tid * ASTR + 202) = hi;
        *(uint16_t*)(sm + SM_A + APLANE + tid * ASTR + 202) = lo;
    }
    __syncthreads();

    float creg[4][7];
#pragma unroll
    for (int mt = 0; mt < 4; mt++)
#pragma unroll
        for (int ti = 0; ti < 7; ti++) creg[mt][ti] = 0.f;

    float y[NP];
#pragma unroll
    for (int q = 0; q < NP; q++) y[q] = 0.f;

    // ==================== layer 1: 30 steps, 1 sync/step ====================
#pragma unroll 1
    for (int t = 0; t < T_STEPS; t++) {
        const uint32_t rAH = (t & 1) ? aAH1 : aAH0;
        const uint32_t rAL = (t & 1) ? aAL1 : aAL0;
        const uint32_t wOff = SM_A + (uint32_t)((t + 1) & 1) * ABUF;

        float acc[4][7][4];
#pragma unroll
        for (int mt = 0; mt < 4; mt++)
#pragma unroll
            for (int ti = 0; ti < 7; ti++)
#pragma unroll
                for (int e = 0; e < 4; e++) acc[mt][ti][e] = 0.f;

        if (warp < 2) {
            gemm_step<7>(acc, rAH, rAL, aB, start);
            lstm_epi<7>(acc, creg, sm, wOff, wOff + APLANE, start, lane);
        } else {
            gemm_step<6>(acc, rAH, rAL, aB, start);
            lstm_epi<6>(acc, creg, sm, wOff, wOff + APLANE, start, lane);
        }
        if (tid < MROWS) {
            float xv = (t < T_STEPS - 1) ? x[(t + 1) * BATCH + b0 + tid] : 0.f;
            uint16_t hi, lo; split_bf16(xv, hi, lo);
            *(uint16_t*)(sm + wOff + tid * ASTR + 202) = hi;
            *(uint16_t*)(sm + wOff + APLANE + tid * ASTR + 202) = lo;
        }
        __syncthreads();
    }
    // h_last now in parity buffer 0 (T_STEPS even)

    // ==================== layer-2 input GEMM (once) ====================
    fill_B(sm, Wih2, bih2, bhh2, (const float*)nullptr, tid);
    __syncthreads();
    {
        float acc[4][7][4];
#pragma unroll
        for (int mt = 0; mt < 4; mt++)
#pragma unroll
            for (int ti = 0; ti < 7; ti++)
#pragma unroll
                for (int e = 0; e < 4; e++) acc[mt][ti][e] = 0.f;
        if (warp < 2) gemm_step<7>(acc, aAH0, aAL0, aB, start);
        else          gemm_step<6>(acc, aAH0, aAL0, aB, start);
        float4* slot = &g_in2[((size_t)blockIdx.x * NTHREADS + tid) * 28];
#pragma unroll
        for (int mt = 0; mt < 4; mt++)
            for (int ti = 0; ti < count; ti++)
                slot[mt * 7 + ti] = make_float4(acc[mt][ti][0], acc[mt][ti][1],
                                                acc[mt][ti][2], acc[mt][ti][3]);
    }
    __syncthreads();
    fill_B(sm, Whh2, (const float*)nullptr, (const float*)nullptr,
           (const float*)nullptr, tid);
    __syncthreads();

    // ==================== layer 2: 7 steps + fused FC2 ====================
    const float4* slot = &g_in2[((size_t)blockIdx.x * NTHREADS + tid) * 28];
#pragma unroll 1
    for (int ps = 0; ps < NP; ps++) {
        const uint32_t rAH = (ps & 1) ? aAH1 : aAH0;
        const uint32_t rAL = (ps & 1) ? aAL1 : aAL0;
        const uint32_t wOff = SM_A + (uint32_t)((ps + 1) & 1) * ABUF;

        float acc[4][7][4];
#pragma unroll
        for (int mt = 0; mt < 4; mt++)
#pragma unroll
            for (int ti = 0; ti < 7; ti++) {
                float4 v = (ti < count) ? slot[mt * 7 + ti] : make_float4(0.f, 0.f, 0.f, 0.f);
                acc[mt][ti][0] = v.x; acc[mt][ti][1] = v.y;
                acc[mt][ti][2] = v.z; acc[mt][ti][3] = v.w;
            }

        if (warp < 2) {
            gemm_step<7>(acc, rAH, rAL, aB, start);
            lstm_epi<7>(acc, creg, sm, wOff, wOff + APLANE, start, lane);
        } else {
            gemm_step<6>(acc, rAH, rAL, aB, start);
            lstm_epi<6>(acc, creg, sm, wOff, wOff + APLANE, start, lane);
        }
        __syncthreads();

        // stage W2 slice for this ps, then FC2 partial
        float* w2s = (float*)(sm + SM_W2S);
        for (int i = tid; i < 700; i += NTHREADS)
            w2s[i] = W2[(i / 100) * (NP * 100) + ps * 100 + (i % 100)];
        __syncthreads();

        if (tid < 2 * MROWS) {
            int row = tid >> 1;
            int j0  = (tid & 1) * 50;
#pragma unroll 2
            for (int jj = 0; jj < 50; jj++) {
                int j = j0 + jj;
                float h = __bfloat162float(*(const __nv_bfloat16*)(sm + wOff + row * ASTR + j * 2)) +
                          __bfloat162float(*(const __nv_bfloat16*)(sm + wOff + APLANE + row * ASTR + j * 2));
#pragma unroll
                for (int q = 0; q < NP; q++)
                    y[q] = fmaf(h, w2s[q * 100 + j], y[q]);
            }
        }
    }

    // ==================== output ====================
    if (tid < 2 * MROWS) {
        int row = tid >> 1;
#pragma unroll
        for (int q = 0; q < NP; q++) {
            float v = y[q] + __shfl_xor_sync(0xffffffffu, y[q], 1);
            if ((tid & 1) == 0)
                out[(size_t)(b0 + row) * NP + q] = sigf(v + b2[q]);
        }
    }
}

// ============================ launch ============================
extern "C" void kernel_launch(void* const* d_in, const int* in_sizes, int n_in,
                              void* d_out, int out_size) {
    const float* x    = (const float*)d_in[0];
    const float* W1   = (const float*)d_in[1];
    const float* b1   = (const float*)d_in[2];
    const float* Wih1 = (const float*)d_in[3];
    const float* Whh1 = (const float*)d_in[4];
    const float* bih1 = (const float*)d_in[5];
    const float* bhh1 = (const float*)d_in[6];
    const float* Wih2 = (const float*)d_in[7];
    const float* Whh2 = (const float*)d_in[8];
    const float* bih2 = (const float*)d_in[9];
    const float* bhh2 = (const float*)d_in[10];
    const float* W2   = (const float*)d_in[11];
    const float* b2   = (const float*)d_in[12];
    float* out = (float*)d_out;

    cudaFuncSetAttribute(lstm_hmma_kernel,
                         cudaFuncAttributeMaxDynamicSharedMemorySize, SMEM_BYTES);

    precompute_kernel<<<1, 512>>>(W1, b1, Wih1, bih1, bhh1);
    lstm_hmma_kernel<<<NCTAS, NTHREADS, SMEM_BYTES>>>(
        x, Whh1, Wih2, Whh2, bih2, bhh2, W2, b2, out);
}

// round 8
// speedup vs baseline: 4.1531x; 1.1555x over previous
#include <cuda_runtime.h>
#include <cuda_bf16.h>
#include <cstdint>

#define T_STEPS 30
#define BATCH   16384
#define NP      7
#define MROWS   64
#define NTHREADS 512
#define NCTAS   (BATCH / MROWS)     // 256

#define BSTR    208                 // B row stride bytes (104 halves), conflict-free ldsm
#define ASTR    240                 // A(h) row stride bytes (120 halves), conflict-free ldsm

// smem byte offsets
#define SM_BH  0                    // B hi: 400 x 208 = 83200
#define SM_BL  83200                // B lo: 83200
#define SM_A   166400               // A planes: [AH0|AL0|AH1|AL1], each 64*240=15360
#define APLANE 15360
#define ABUF   30720                // one parity buffer (hi+lo)
#define SM_W2S 227840               // staged W2 slice for current ps: 700 floats
#define SMEM_BYTES 230640

// ---- device scratch (allocation-free) ----
__device__ float  g_v1[400];                 // Wih1 @ W1
__device__ float  g_u1[400];                 // Wih1 @ b1 + bih1 + bhh1
__device__ float4 g_in2[(size_t)NCTAS * NTHREADS * 14];   // layer-2 input pre-acts (frag layout)

// ============================ helpers ============================
__device__ __forceinline__ uint32_t sptr(const void* p) {
    uint32_t a;
    asm("{ .reg .u64 t; cvta.to.shared.u64 t, %1; cvt.u32.u64 %0, t; }" : "=r"(a) : "l"(p));
    return a;
}
__device__ __forceinline__ float tanha(float x) {
    float y; asm("tanh.approx.f32 %0, %1;" : "=f"(y) : "f"(x)); return y;
}
__device__ __forceinline__ float sigf(float x) { return fmaf(tanha(0.5f * x), 0.5f, 0.5f); }

__device__ __forceinline__ void ldsm_x4(uint32_t* r, uint32_t a) {
    asm volatile("ldmatrix.sync.aligned.m8n8.x4.shared.b16 {%0,%1,%2,%3}, [%4];"
                 : "=r"(r[0]), "=r"(r[1]), "=r"(r[2]), "=r"(r[3]) : "r"(a));
}
__device__ __forceinline__ void mma_bf16(float* d, const uint32_t* a, const uint32_t* b) {
    asm volatile("mma.sync.aligned.m16n8k16.row.col.f32.bf16.bf16.f32 "
                 "{%0,%1,%2,%3}, {%4,%5,%6,%7}, {%8,%9}, {%0,%1,%2,%3};"
                 : "+f"(d[0]), "+f"(d[1]), "+f"(d[2]), "+f"(d[3])
                 : "r"(a[0]), "r"(a[1]), "r"(a[2]), "r"(a[3]), "r"(b[0]), "r"(b[1]));
}
__device__ __forceinline__ void split_bf16(float v, uint16_t& hi, uint16_t& lo) {
    __nv_bfloat16 h = __float2bfloat16(v);
    hi = __bfloat16_as_ushort(h);
    lo = __bfloat16_as_ushort(__float2bfloat16(v - __bfloat162float(h)));
}

// ============================ precompute (tiny) ============================
__global__ void precompute_kernel(const float* __restrict__ W1,
                                  const float* __restrict__ b1,
                                  const float* __restrict__ Wih1,
                                  const float* __restrict__ bih1,
                                  const float* __restrict__ bhh1) {
    int j = blockIdx.x * blockDim.x + threadIdx.x;
    if (j < 400) {
        float v = 0.f, u = 0.f;
        for (int k = 0; k < 100; k++) {
            float w = Wih1[j * 100 + k];
            v += w * W1[k];
            u += w * b1[k];
        }
        g_v1[j] = v;
        g_u1[j] = u + bih1[j] + bhh1[j];
    }
}

// B fill: row n = 4*j + g <- source gate-row (g*100 + j).
// K cols: 0..99 weights, 100 = u1(+u2), 101 = v, 102..103 zero.
__device__ void fill_B(char* sm, const float* __restrict__ W,
                       const float* __restrict__ ua, const float* __restrict__ ub,
                       const float* __restrict__ v, int tid) {
    for (int idx = tid; idx < 400 * 104; idx += NTHREADS) {
        int n = idx / 104, k = idx - n * 104;
        int srow = (n & 3) * 100 + (n >> 2);
        float val = 0.f;
        if (k < 100)       val = W[srow * 100 + k];
        else if (k == 100) { if (ua) val = ua[srow]; if (ub) val += ub[srow]; }
        else if (k == 101) { if (v)  val = v[srow]; }
        uint16_t hi, lo; split_bf16(val, hi, lo);
        *(uint16_t*)(sm + SM_BH + n * BSTR + k * 2) = hi;
        *(uint16_t*)(sm + SM_BL + n * BSTR + k * 2) = lo;
    }
}

// 3-term split-bf16 GEMM; warp owns 2 m16-tiles x COUNT n8-tiles.
// B hi+lo fetched in ONE ldsm_x4 (lanes 0-15 hi plane, 16-31 lo plane).
template<int COUNT>
__device__ __forceinline__ void gemm_step(float acc[2][7][4],
                                          uint32_t aAH, uint32_t aAL,
                                          uint32_t aB, int start) {
#pragma unroll
    for (int ch = 0; ch < 7; ch++) {
        uint32_t ah[2][4], al[2][4];
#pragma unroll
        for (int mi = 0; mi < 2; mi++) {
            ldsm_x4(ah[mi], aAH + mi * (16 * ASTR) + ch * 32);
            ldsm_x4(al[mi], aAL + mi * (16 * ASTR) + ch * 32);
        }
#pragma unroll
        for (int ti = 0; ti < COUNT; ti++) {
            uint32_t b[4];   // b[0..1] = Bh frag, b[2..3] = Bl frag
            ldsm_x4(b, aB + (uint32_t)(start + ti) * (8 * BSTR) + ch * 32);
#pragma unroll
            for (int mi = 0; mi < 2; mi++) {
                mma_bf16(acc[mi][ti], ah[mi], b);       // hh * Bh
                mma_bf16(acc[mi][ti], al[mi], b);       // hl * Bh
                mma_bf16(acc[mi][ti], ah[mi], b + 2);   // hh * Bl
            }
        }
    }
}

// epilogue: gate exchange via shfl, LSTM cell math, h -> write buffer (bf16 hi/lo)
template<int COUNT>
__device__ __forceinline__ void lstm_epi(float acc[2][7][4], float creg[2][7],
                                         char* sm, uint32_t AHw, uint32_t ALw,
                                         int start, int mtbase, int lane) {
    const int cq = lane & 3;
    const int rq = lane >> 2;
    const bool even = (cq & 1) == 0;
#pragma unroll
    for (int mi = 0; mi < 2; mi++)
#pragma unroll
        for (int ti = 0; ti < COUNT; ti++) {
            float* d = acc[mi][ti];
            float s0 = even ? d[2] : d[0];
            float s1 = even ? d[3] : d[1];
            float e0 = __shfl_xor_sync(0xffffffffu, s0, 1);
            float e1 = __shfl_xor_sync(0xffffffffu, s1, 1);
            float gi, gf, gg, go;
            if (even) { gi = d[0]; gf = d[1]; gg = e0; go = e1; }
            else      { gi = e0;  gf = e1;  gg = d[2]; go = d[3]; }
            float cc = creg[mi][ti];
            cc = sigf(gf) * cc + sigf(gi) * tanha(gg);
            creg[mi][ti] = cc;
            float h = sigf(go) * tanha(cc);
            int row  = (mtbase + mi) * 16 + rq + (even ? 0 : 8);
            int unit = 2 * (start + ti) + (cq >> 1);
            uint16_t hi, lo; split_bf16(h, hi, lo);
            *(uint16_t*)(sm + AHw + row * ASTR + unit * 2) = hi;
            *(uint16_t*)(sm + ALw + row * ASTR + unit * 2) = lo;
        }
}

// ============================ main kernel ============================
__global__ __launch_bounds__(NTHREADS, 1)
void lstm_hmma_kernel(const float* __restrict__ x,
                      const float* __restrict__ Whh1,
                      const float* __restrict__ Wih2,
                      const float* __restrict__ Whh2,
                      const float* __restrict__ bih2,
                      const float* __restrict__ bhh2,
                      const float* __restrict__ W2,
                      const float* __restrict__ b2,
                      float* __restrict__ out) {
    extern __shared__ char sm[];
    const uint32_t smb = sptr(sm);
    const int tid  = threadIdx.x;
    const int warp = tid >> 5;
    const int lane = tid & 31;
    const int b0   = blockIdx.x * MROWS;

    // warp decomposition: 8 N-slices x 2 M-halves
    const int ns     = warp & 7;          // n-slice id
    const int mhalf  = warp >> 3;         // 0 or 1
    const int mtbase = mhalf * 2;         // first m16-tile
    // slices: ns 0,1 -> 7 tiles; ns 2..7 -> 6 tiles (2*7 + 6*6 = 50)
    const int start = (ns < 2) ? ns * 7 : 14 + (ns - 2) * 6;
    const int count = (ns < 2) ? 7 : 6;

    // ldmatrix lane addresses (A base includes the M-half offset)
    const uint32_t aAH0 = smb + SM_A + (uint32_t)mtbase * (16 * ASTR)
                        + (uint32_t)(lane & 15) * ASTR + ((lane >> 4) ? 16u : 0u);
    const uint32_t aAL0 = aAH0 + APLANE;
    const uint32_t aAH1 = aAH0 + ABUF;
    const uint32_t aAL1 = aAH1 + APLANE;
    const uint32_t aB   = smb + ((lane < 16) ? SM_BH : SM_BL)
                        + (uint32_t)(lane & 7) * BSTR + (((lane >> 3) & 1) ? 16u : 0u);

    // ---- prologue ----
    fill_B(sm, Whh1, g_u1, (const float*)nullptr, g_v1, tid);
    for (int i = tid; i < (2 * ABUF) / 4; i += NTHREADS)
        *(uint32_t*)(sm + SM_A + i * 4) = 0u;
    __syncthreads();
    if (tid < MROWS) {
        // col100 = 1.0 in both parity buffers; col101 = x[0] in buffer 0
        *(uint16_t*)(sm + SM_A + tid * ASTR + 200) = 0x3F80u;
        *(uint16_t*)(sm + SM_A + ABUF + tid * ASTR + 200) = 0x3F80u;
        uint16_t hi, lo; split_bf16(x[b0 + tid], hi, lo);
        *(uint16_t*)(sm + SM_A + tid * ASTR + 202) = hi;
        *(uint16_t*)(sm + SM_A + APLANE + tid * ASTR + 202) = lo;
    }
    __syncthreads();

    float creg[2][7];
#pragma unroll
    for (int mi = 0; mi < 2; mi++)
#pragma unroll
        for (int ti = 0; ti < 7; ti++) creg[mi][ti] = 0.f;

    float y[NP];
#pragma unroll
    for (int q = 0; q < NP; q++) y[q] = 0.f;

    // ==================== layer 1: 30 steps, 1 sync/step ====================
#pragma unroll 1
    for (int t = 0; t < T_STEPS; t++) {
        const uint32_t rAH = (t & 1) ? aAH1 : aAH0;
        const uint32_t rAL = (t & 1) ? aAL1 : aAL0;
        const uint32_t wOff = SM_A + (uint32_t)((t + 1) & 1) * ABUF;

        float acc[2][7][4];
#pragma unroll
        for (int mi = 0; mi < 2; mi++)
#pragma unroll
            for (int ti = 0; ti < 7; ti++)
#pragma unroll
                for (int e = 0; e < 4; e++) acc[mi][ti][e] = 0.f;

        if (ns < 2) {
            gemm_step<7>(acc, rAH, rAL, aB, start);
            lstm_epi<7>(acc, creg, sm, wOff, wOff + APLANE, start, mtbase, lane);
        } else {
            gemm_step<6>(acc, rAH, rAL, aB, start);
            lstm_epi<6>(acc, creg, sm, wOff, wOff + APLANE, start, mtbase, lane);
        }
        if (tid < MROWS) {
            float xv = (t < T_STEPS - 1) ? x[(t + 1) * BATCH + b0 + tid] : 0.f;
            uint16_t hi, lo; split_bf16(xv, hi, lo);
            *(uint16_t*)(sm + wOff + tid * ASTR + 202) = hi;
            *(uint16_t*)(sm + wOff + APLANE + tid * ASTR + 202) = lo;
        }
        __syncthreads();
    }
    // h_last now in parity buffer 0 (T_STEPS even)

    // ==================== layer-2 input GEMM (once) ====================
    fill_B(sm, Wih2, bih2, bhh2, (const float*)nullptr, tid);
    __syncthreads();
    {
        float acc[2][7][4];
#pragma unroll
        for (int mi = 0; mi < 2; mi++)
#pragma unroll
            for (int ti = 0; ti < 7; ti++)
#pragma unroll
                for (int e = 0; e < 4; e++) acc[mi][ti][e] = 0.f;
        if (ns < 2) gemm_step<7>(acc, aAH0, aAL0, aB, start);
        else        gemm_step<6>(acc, aAH0, aAL0, aB, start);
        float4* slot = &g_in2[((size_t)blockIdx.x * NTHREADS + tid) * 14];
#pragma unroll
        for (int mi = 0; mi < 2; mi++)
            for (int ti = 0; ti < count; ti++)
                slot[mi * 7 + ti] = make_float4(acc[mi][ti][0], acc[mi][ti][1],
                                                acc[mi][ti][2], acc[mi][ti][3]);
    }
    __syncthreads();
    fill_B(sm, Whh2, (const float*)nullptr, (const float*)nullptr,
           (const float*)nullptr, tid);
    __syncthreads();

    // ==================== layer 2: 7 steps + fused FC2 ====================
    const float4* slot = &g_in2[((size_t)blockIdx.x * NTHREADS + tid) * 14];
#pragma unroll 1
    for (int ps = 0; ps < NP; ps++) {
        const uint32_t rAH = (ps & 1) ? aAH1 : aAH0;
        const uint32_t rAL = (ps & 1) ? aAL1 : aAL0;
        const uint32_t wOff = SM_A + (uint32_t)((ps + 1) & 1) * ABUF;

        float acc[2][7][4];
#pragma unroll
        for (int mi = 0; mi < 2; mi++)
#pragma unroll
            for (int ti = 0; ti < 7; ti++) {
                float4 v = (ti < count) ? slot[mi * 7 + ti] : make_float4(0.f, 0.f, 0.f, 0.f);
                acc[mi][ti][0] = v.x; acc[mi][ti][1] = v.y;
                acc[mi][ti][2] = v.z; acc[mi][ti][3] = v.w;
            }

        if (ns < 2) {
            gemm_step<7>(acc, rAH, rAL, aB, start);
            lstm_epi<7>(acc, creg, sm, wOff, wOff + APLANE, start, mtbase, lane);
        } else {
            gemm_step<6>(acc, rAH, rAL, aB, start);
            lstm_epi<6>(acc, creg, sm, wOff, wOff + APLANE, start, mtbase, lane);
        }
        __syncthreads();

        // stage W2 slice for this ps, then FC2 partial
        float* w2s = (float*)(sm + SM_W2S);
        for (int i = tid; i < 700; i += NTHREADS)
            w2s[i] = W2[(i / 100) * (NP * 100) + ps * 100 + (i % 100)];
        __syncthreads();

        if (tid < 2 * MROWS) {
            int row = tid >> 1;
            int j0  = (tid & 1) * 50;
#pragma unroll 2
            for (int jj = 0; jj < 50; jj++) {
                int j = j0 + jj;
                float h = __bfloat162float(*(const __nv_bfloat16*)(sm + wOff + row * ASTR + j * 2)) +
                          __bfloat162float(*(const __nv_bfloat16*)(sm + wOff + APLANE + row * ASTR + j * 2));
#pragma unroll
                for (int q = 0; q < NP; q++)
                    y[q] = fmaf(h, w2s[q * 100 + j], y[q]);
            }
        }
    }

    // ==================== output ====================
    if (tid < 2 * MROWS) {
        int row = tid >> 1;
#pragma unroll
        for (int q = 0; q < NP; q++) {
            float v = y[q] + __shfl_xor_sync(0xffffffffu, y[q], 1);
            if ((tid & 1) == 0)
                out[(size_t)(b0 + row) * NP + q] = sigf(v + b2[q]);
        }
    }
}

// ============================ launch ============================
extern "C" void kernel_launch(void* const* d_in, const int* in_sizes, int n_in,
                              void* d_out, int out_size) {
    const float* x    = (const float*)d_in[0];
    const float* W1   = (const float*)d_in[1];
    const float* b1   = (const float*)d_in[2];
    const float* Wih1 = (const float*)d_in[3];
    const float* Whh1 = (const float*)d_in[4];
    const float* bih1 = (const float*)d_in[5];
    const float* bhh1 = (const float*)d_in[6];
    const float* Wih2 = (const float*)d_in[7];
    const float* Whh2 = (const float*)d_in[8];
    const float* bih2 = (const float*)d_in[9];
    const float* bhh2 = (const float*)d_in[10];
    const float* W2   = (const float*)d_in[11];
    const float* b2   = (const float*)d_in[12];
    float* out = (float*)d_out;

    cudaFuncSetAttribute(lstm_hmma_kernel,
                         cudaFuncAttributeMaxDynamicSharedMemorySize, SMEM_BYTES);

    precompute_kernel<<<1, 512>>>(W1, b1, Wih1, bih1, bhh1);
    lstm_hmma_kernel<<<NCTAS, NTHREADS, SMEM_BYTES>>>(
        x, Whh1, Wih2, Whh2, bih2, bhh2, W2, b2, out);
}

// round 9
// speedup vs baseline: 5.0846x; 1.2243x over previous
#include <cuda_runtime.h>
#include <cuda_fp16.h>
#include <cstdint>

#define T_STEPS 30
#define BATCH   16384
#define NP      7
#define MROWS   64
#define NTHREADS 512
#define NCTAS   (BATCH / MROWS)     // 256

#define BSTR    208                 // B row stride bytes (104 halves), conflict-free ldsm
#define ASTR    240                 // A(h) row stride bytes (120 halves), conflict-free ldsm

// smem byte offsets
#define SM_BH  0                    // B hi: 400 x 208 = 83200
#define SM_BL  83200                // B lo: 83200
#define SM_A   166400               // A parity buffers: [A0|A1], each 64*240=15360
#define ABUF   15360
#define SM_W2S 197120               // staged W2 slice for current ps: 700 floats
#define SMEM_BYTES 199920

// ---- device scratch (allocation-free) ----
__device__ float  g_v1[400];                 // Wih1 @ W1
__device__ float  g_u1[400];                 // Wih1 @ b1 + bih1 + bhh1
__device__ float4 g_in2[(size_t)NCTAS * NTHREADS * 14];   // layer-2 input pre-acts (frag layout)

// ============================ helpers ============================
__device__ __forceinline__ uint32_t sptr(const void* p) {
    uint32_t a;
    asm("{ .reg .u64 t; cvta.to.shared.u64 t, %1; cvt.u32.u64 %0, t; }" : "=r"(a) : "l"(p));
    return a;
}
__device__ __forceinline__ float tanha(float x) {
    float y; asm("tanh.approx.f32 %0, %1;" : "=f"(y) : "f"(x)); return y;
}
__device__ __forceinline__ float sigf(float x) { return fmaf(tanha(0.5f * x), 0.5f, 0.5f); }

__device__ __forceinline__ void ldsm_x4(uint32_t* r, uint32_t a) {
    asm volatile("ldmatrix.sync.aligned.m8n8.x4.shared.b16 {%0,%1,%2,%3}, [%4];"
                 : "=r"(r[0]), "=r"(r[1]), "=r"(r[2]), "=r"(r[3]) : "r"(a));
}
__device__ __forceinline__ void mma_f16(float* d, const uint32_t* a, const uint32_t* b) {
    asm volatile("mma.sync.aligned.m16n8k16.row.col.f32.f16.f16.f32 "
                 "{%0,%1,%2,%3}, {%4,%5,%6,%7}, {%8,%9}, {%0,%1,%2,%3};"
                 : "+f"(d[0]), "+f"(d[1]), "+f"(d[2]), "+f"(d[3])
                 : "r"(a[0]), "r"(a[1]), "r"(a[2]), "r"(a[3]), "r"(b[0]), "r"(b[1]));
}
__device__ __forceinline__ void split_f16(float v, uint16_t& hi, uint16_t& lo) {
    __half h = __float2half_rn(v);
    hi = __half_as_ushort(h);
    lo = __half_as_ushort(__float2half_rn(v - __half2float(h)));
}

// ============================ precompute (tiny) ============================
__global__ void precompute_kernel(const float* __restrict__ W1,
                                  const float* __restrict__ b1,
                                  const float* __restrict__ Wih1,
                                  const float* __restrict__ bih1,
                                  const float* __restrict__ bhh1) {
    int j = blockIdx.x * blockDim.x + threadIdx.x;
    if (j < 400) {
        float v = 0.f, u = 0.f;
        for (int k = 0; k < 100; k++) {
            float w = Wih1[j * 100 + k];
            v += w * W1[k];
            u += w * b1[k];
        }
        g_v1[j] = v;
        g_u1[j] = u + bih1[j] + bhh1[j];
    }
}

// B fill: row n = 4*j + g <- source gate-row (g*100 + j).
// K cols: 0..99 weights, 100 = u1(+u2), 101 = v, 102..103 zero.
// Each entry split fp32 -> fp16 hi plane + fp16 lo plane.
__device__ void fill_B(char* sm, const float* __restrict__ W,
                       const float* __restrict__ ua, const float* __restrict__ ub,
                       const float* __restrict__ v, int tid) {
    for (int idx = tid; idx < 400 * 104; idx += NTHREADS) {
        int n = idx / 104, k = idx - n * 104;
        int srow = (n & 3) * 100 + (n >> 2);
        float val = 0.f;
        if (k < 100)       val = W[srow * 100 + k];
        else if (k == 100) { if (ua) val = ua[srow]; if (ub) val += ub[srow]; }
        else if (k == 101) { if (v)  val = v[srow]; }
        uint16_t hi, lo; split_f16(val, hi, lo);
        *(uint16_t*)(sm + SM_BH + n * BSTR + k * 2) = hi;
        *(uint16_t*)(sm + SM_BL + n * BSTR + k * 2) = lo;
    }
}

// 2-term fp16 GEMM: acc += A*Bh + A*Bl; warp owns 2 m16-tiles x COUNT n8-tiles.
// B hi+lo fetched in ONE ldsm_x4 (lanes 0-15 hi plane, 16-31 lo plane).
template<int COUNT>
__device__ __forceinline__ void gemm_step(float acc[2][7][4],
                                          uint32_t aA, uint32_t aB, int start) {
#pragma unroll
    for (int ch = 0; ch < 7; ch++) {
        uint32_t ah[2][4];
#pragma unroll
        for (int mi = 0; mi < 2; mi++)
            ldsm_x4(ah[mi], aA + mi * (16 * ASTR) + ch * 32);
#pragma unroll
        for (int ti = 0; ti < COUNT; ti++) {
            uint32_t b[4];   // b[0..1] = Bh frag, b[2..3] = Bl frag
            ldsm_x4(b, aB + (uint32_t)(start + ti) * (8 * BSTR) + ch * 32);
#pragma unroll
            for (int mi = 0; mi < 2; mi++) {
                mma_f16(acc[mi][ti], ah[mi], b);       // h * Bh
                mma_f16(acc[mi][ti], ah[mi], b + 2);   // h * Bl
            }
        }
    }
}

// epilogue: gate exchange via shfl, LSTM cell math, h -> write buffer (fp16)
template<int COUNT>
__device__ __forceinline__ void lstm_epi(float acc[2][7][4], float creg[2][7],
                                         char* sm, uint32_t Aw,
                                         int start, int mtbase, int lane) {
    const int cq = lane & 3;
    const int rq = lane >> 2;
    const bool even = (cq & 1) == 0;
#pragma unroll
    for (int mi = 0; mi < 2; mi++)
#pragma unroll
        for (int ti = 0; ti < COUNT; ti++) {
            float* d = acc[mi][ti];
            float s0 = even ? d[2] : d[0];
            float s1 = even ? d[3] : d[1];
            float e0 = __shfl_xor_sync(0xffffffffu, s0, 1);
            float e1 = __shfl_xor_sync(0xffffffffu, s1, 1);
            float gi, gf, gg, go;
            if (even) { gi = d[0]; gf = d[1]; gg = e0; go = e1; }
            else      { gi = e0;  gf = e1;  gg = d[2]; go = d[3]; }
            float cc = creg[mi][ti];
            cc = sigf(gf) * cc + sigf(gi) * tanha(gg);
            creg[mi][ti] = cc;
            float h = sigf(go) * tanha(cc);
            int row  = (mtbase + mi) * 16 + rq + (even ? 0 : 8);
            int unit = 2 * (start + ti) + (cq >> 1);
            *(uint16_t*)(sm + Aw + row * ASTR + unit * 2) =
                __half_as_ushort(__float2half_rn(h));
        }
}

// ============================ main kernel ============================
__global__ __launch_bounds__(NTHREADS, 1)
void lstm_hmma_kernel(const float* __restrict__ x,
                      const float* __restrict__ Whh1,
                      const float* __restrict__ Wih2,
                      const float* __restrict__ Whh2,
                      const float* __restrict__ bih2,
                      const float* __restrict__ bhh2,
                      const float* __restrict__ W2,
                      const float* __restrict__ b2,
                      float* __restrict__ out) {
    extern __shared__ char sm[];
    const uint32_t smb = sptr(sm);
    const int tid  = threadIdx.x;
    const int warp = tid >> 5;
    const int lane = tid & 31;
    const int b0   = blockIdx.x * MROWS;

    // warp decomposition: 8 N-slices x 2 M-halves
    const int ns     = warp & 7;          // n-slice id
    const int mhalf  = warp >> 3;         // 0 or 1
    const int mtbase = mhalf * 2;         // first m16-tile
    // slices: ns 0,1 -> 7 tiles; ns 2..7 -> 6 tiles (2*7 + 6*6 = 50)
    const int start = (ns < 2) ? ns * 7 : 14 + (ns - 2) * 6;
    const int count = (ns < 2) ? 7 : 6;

    // ldmatrix lane addresses (A base includes the M-half offset)
    const uint32_t aA0 = smb + SM_A + (uint32_t)mtbase * (16 * ASTR)
                       + (uint32_t)(lane & 15) * ASTR + ((lane >> 4) ? 16u : 0u);
    const uint32_t aA1 = aA0 + ABUF;
    const uint32_t aB  = smb + ((lane < 16) ? SM_BH : SM_BL)
                       + (uint32_t)(lane & 7) * BSTR + (((lane >> 3) & 1) ? 16u : 0u);

    // ---- prologue ----
    fill_B(sm, Whh1, g_u1, (const float*)nullptr, g_v1, tid);
    for (int i = tid; i < (2 * ABUF) / 4; i += NTHREADS)
        *(uint32_t*)(sm + SM_A + i * 4) = 0u;
    __syncthreads();
    if (tid < MROWS) {
        // col100 = 1.0 (fp16) in both parity buffers; col101 = x[0] in buffer 0
        *(uint16_t*)(sm + SM_A + tid * ASTR + 200) = 0x3C00u;
        *(uint16_t*)(sm + SM_A + ABUF + tid * ASTR + 200) = 0x3C00u;
        *(uint16_t*)(sm + SM_A + tid * ASTR + 202) =
            __half_as_ushort(__float2half_rn(x[b0 + tid]));
    }
    __syncthreads();

    float creg[2][7];
#pragma unroll
    for (int mi = 0; mi < 2; mi++)
#pragma unroll
        for (int ti = 0; ti < 7; ti++) creg[mi][ti] = 0.f;

    float y[NP];
#pragma unroll
    for (int q = 0; q < NP; q++) y[q] = 0.f;

    // ==================== layer 1: 30 steps, 1 sync/step ====================
#pragma unroll 1
    for (int t = 0; t < T_STEPS; t++) {
        const uint32_t rA   = (t & 1) ? aA1 : aA0;
        const uint32_t wOff = SM_A + (uint32_t)((t + 1) & 1) * ABUF;

        float acc[2][7][4];
#pragma unroll
        for (int mi = 0; mi < 2; mi++)
#pragma unroll
            for (int ti = 0; ti < 7; ti++)
#pragma unroll
                for (int e = 0; e < 4; e++) acc[mi][ti][e] = 0.f;

        if (ns < 2) {
            gemm_step<7>(acc, rA, aB, start);
            lstm_epi<7>(acc, creg, sm, wOff, start, mtbase, lane);
        } else {
            gemm_step<6>(acc, rA, aB, start);
            lstm_epi<6>(acc, creg, sm, wOff, start, mtbase, lane);
        }
        if (tid < MROWS) {
            float xv = (t < T_STEPS - 1) ? x[(t + 1) * BATCH + b0 + tid] : 0.f;
            *(uint16_t*)(sm + wOff + tid * ASTR + 202) =
                __half_as_ushort(__float2half_rn(xv));
        }
        __syncthreads();
    }
    // h_last now in parity buffer 0 (T_STEPS even)

    // ==================== layer-2 input GEMM (once) ====================
    fill_B(sm, Wih2, bih2, bhh2, (const float*)nullptr, tid);
    __syncthreads();
    {
        float acc[2][7][4];
#pragma unroll
        for (int mi = 0; mi < 2; mi++)
#pragma unroll
            for (int ti = 0; ti < 7; ti++)
#pragma unroll
                for (int e = 0; e < 4; e++) acc[mi][ti][e] = 0.f;
        if (ns < 2) gemm_step<7>(acc, aA0, aB, start);
        else        gemm_step<6>(acc, aA0, aB, start);
        float4* slot = &g_in2[((size_t)blockIdx.x * NTHREADS + tid) * 14];
#pragma unroll
        for (int mi = 0; mi < 2; mi++)
            for (int ti = 0; ti < count; ti++)
                slot[mi * 7 + ti] = make_float4(acc[mi][ti][0], acc[mi][ti][1],
                                                acc[mi][ti][2], acc[mi][ti][3]);
    }
    __syncthreads();
    fill_B(sm, Whh2, (const float*)nullptr, (const float*)nullptr,
           (const float*)nullptr, tid);
    __syncthreads();

    // ==================== layer 2: 7 steps + fused FC2 ====================
    const float4* slot = &g_in2[((size_t)blockIdx.x * NTHREADS + tid) * 14];
#pragma unroll 1
    for (int ps = 0; ps < NP; ps++) {
        const uint32_t rA   = (ps & 1) ? aA1 : aA0;
        const uint32_t wOff = SM_A + (uint32_t)((ps + 1) & 1) * ABUF;

        float acc[2][7][4];
#pragma unroll
        for (int mi = 0; mi < 2; mi++)
#pragma unroll
            for (int ti = 0; ti < 7; ti++) {
                float4 v = (ti < count) ? slot[mi * 7 + ti] : make_float4(0.f, 0.f, 0.f, 0.f);
                acc[mi][ti][0] = v.x; acc[mi][ti][1] = v.y;
                acc[mi][ti][2] = v.z; acc[mi][ti][3] = v.w;
            }

        if (ns < 2) {
            gemm_step<7>(acc, rA, aB, start);
            lstm_epi<7>(acc, creg, sm, wOff, start, mtbase, lane);
        } else {
            gemm_step<6>(acc, rA, aB, start);
            lstm_epi<6>(acc, creg, sm, wOff, start, mtbase, lane);
        }
        __syncthreads();

        // stage W2 slice for this ps, then FC2 partial
        float* w2s = (float*)(sm + SM_W2S);
        for (int i = tid; i < 700; i += NTHREADS)
            w2s[i] = W2[(i / 100) * (NP * 100) + ps * 100 + (i % 100)];
        __syncthreads();

        if (tid < 2 * MROWS) {
            int row = tid >> 1;
            int j0  = (tid & 1) * 50;
#pragma unroll 2
            for (int jj = 0; jj < 50; jj++) {
                int j = j0 + jj;
                float h = __half2float(*(const __half*)(sm + wOff + row * ASTR + j * 2));
#pragma unroll
                for (int q = 0; q < NP; q++)
                    y[q] = fmaf(h, w2s[q * 100 + j], y[q]);
            }
        }
    }

    // ==================== output ====================
    if (tid < 2 * MROWS) {
        int row = tid >> 1;
#pragma unroll
        for (int q = 0; q < NP; q++) {
            float v = y[q] + __shfl_xor_sync(0xffffffffu, y[q], 1);
            if ((tid & 1) == 0)
                out[(size_t)(b0 + row) * NP + q] = sigf(v + b2[q]);
        }
    }
}

// ============================ launch ============================
extern "C" void kernel_launch(void* const* d_in, const int* in_sizes, int n_in,
                              void* d_out, int out_size) {
    const float* x    = (const float*)d_in[0];
    const float* W1   = (const float*)d_in[1];
    const float* b1   = (const float*)d_in[2];
    const float* Wih1 = (const float*)d_in[3];
    const float* Whh1 = (const float*)d_in[4];
    const float* bih1 = (const float*)d_in[5];
    const float* bhh1 = (const float*)d_in[6];
    const float* Wih2 = (const float*)d_in[7];
    const float* Whh2 = (const float*)d_in[8];
    const float* bih2 = (const float*)d_in[9];
    const float* bhh2 = (const float*)d_in[10];
    const float* W2   = (const float*)d_in[11];
    const float* b2   = (const float*)d_in[12];
    float* out = (float*)d_out;

    cudaFuncSetAttribute(lstm_hmma_kernel,
                         cudaFuncAttributeMaxDynamicSharedMemorySize, SMEM_BYTES);

    precompute_kernel<<<1, 512>>>(W1, b1, Wih1, bih1, bhh1);
    lstm_hmma_kernel<<<NCTAS, NTHREADS, SMEM_BYTES>>>(
        x, Whh1, Wih2, Whh2, bih2, bhh2, W2, b2, out);
}

// round 11
// speedup vs baseline: 7.2964x; 1.4350x over previous
#include <cuda_runtime.h>
#include <cuda_fp16.h>
#include <cstdint>

#define T_STEPS 30
#define BATCH   16384
#define NP      7
#define MROWS   64
#define NTHREADS 512
#define NCTAS   (BATCH / MROWS)     // 256

#define BSTR    208                 // B row stride bytes (104 halves), conflict-free ldsm
#define ASTR    240                 // A(h) row stride bytes (120 halves), conflict-free ldsm
                                    // A cols 102..119 stay ZERO -> annihilate B overread in ch6

// smem byte offsets
#define SM_B   0                    // B: 400 x 208 = 83200 (single fp16 plane)
#define SM_A   83200                // A parity buffers: [A0|A1], each 64*240=15360
#define ABUF   15360
#define SM_W2S 113920               // staged W2 slice for current ps: 700 floats
#define SMEM_BYTES 116720

// ---- device scratch (allocation-free) ----
__device__ float  g_v1[400];                 // Wih1 @ W1
__device__ float  g_u1[400];                 // Wih1 @ b1 + bih1 + bhh1
__device__ float4 g_in2[(size_t)NCTAS * NTHREADS * 14];   // layer-2 input pre-acts (frag layout)

// ============================ helpers ============================
__device__ __forceinline__ uint32_t sptr(const void* p) {
    uint32_t a;
    asm("{ .reg .u64 t; cvta.to.shared.u64 t, %1; cvt.u32.u64 %0, t; }" : "=r"(a) : "l"(p));
    return a;
}
__device__ __forceinline__ float tanha(float x) {
    float y; asm("tanh.approx.f32 %0, %1;" : "=f"(y) : "f"(x)); return y;
}
__device__ __forceinline__ float sigf(float x) { return fmaf(tanha(0.5f * x), 0.5f, 0.5f); }

__device__ __forceinline__ void ldsm_x4(uint32_t* r, uint32_t a) {
    asm volatile("ldmatrix.sync.aligned.m8n8.x4.shared.b16 {%0,%1,%2,%3}, [%4];"
                 : "=r"(r[0]), "=r"(r[1]), "=r"(r[2]), "=r"(r[3]) : "r"(a));
}
__device__ __forceinline__ void ldsm_x2(uint32_t* r, uint32_t a) {
    asm volatile("ldmatrix.sync.aligned.m8n8.x2.shared.b16 {%0,%1}, [%2];"
                 : "=r"(r[0]), "=r"(r[1]) : "r"(a));
}
__device__ __forceinline__ void mma_f16(float* d, const uint32_t* a, const uint32_t* b) {
    asm volatile("mma.sync.aligned.m16n8k16.row.col.f32.f16.f16.f32 "
                 "{%0,%1,%2,%3}, {%4,%5,%6,%7}, {%8,%9}, {%0,%1,%2,%3};"
                 : "+f"(d[0]), "+f"(d[1]), "+f"(d[2]), "+f"(d[3])
                 : "r"(a[0]), "r"(a[1]), "r"(a[2]), "r"(a[3]), "r"(b[0]), "r"(b[1]));
}

// ============================ precompute (tiny) ============================
__global__ void precompute_kernel(const float* __restrict__ W1,
                                  const float* __restrict__ b1,
                                  const float* __restrict__ Wih1,
                                  const float* __restrict__ bih1,
                                  const float* __restrict__ bhh1) {
    int j = blockIdx.x * blockDim.x + threadIdx.x;
    if (j < 400) {
        float v = 0.f, u = 0.f;
        for (int k = 0; k < 100; k++) {
            float w = Wih1[j * 100 + k];
            v += w * W1[k];
            u += w * b1[k];
        }
        g_v1[j] = v;
        g_u1[j] = u + bih1[j] + bhh1[j];
    }
}

// B fill: row n = 4*j + g <- source gate-row (g*100 + j).
// K cols: 0..99 weights, 100 = u1(+u2), 101 = v, 102..103 zero. Single fp16 plane.
__device__ void fill_B(char* sm, const float* __restrict__ W,
                       const float* __restrict__ ua, const float* __restrict__ ub,
                       const float* __restrict__ v, int tid) {
    for (int idx = tid; idx < 400 * 104; idx += NTHREADS) {
        int n = idx / 104, k = idx - n * 104;
        int srow = (n & 3) * 100 + (n >> 2);
        float val = 0.f;
        if (k < 100)       val = W[srow * 100 + k];
        else if (k == 100) { if (ua) val = ua[srow]; if (ub) val += ub[srow]; }
        else if (k == 101) { if (v)  val = v[srow]; }
        *(uint16_t*)(sm + SM_B + n * BSTR + k * 2) =
            __half_as_ushort(__float2half_rn(val));
    }
}

// 1-term fp16 GEMM: acc += A*B; warp owns 2 m16-tiles x COUNT n8-tiles.
template<int COUNT>
__device__ __forceinline__ void gemm_step(float acc[2][7][4],
                                          uint32_t aA, uint32_t aB, int start) {
#pragma unroll
    for (int ch = 0; ch < 7; ch++) {
        uint32_t ah[2][4];
#pragma unroll
        for (int mi = 0; mi < 2; mi++)
            ldsm_x4(ah[mi], aA + mi * (16 * ASTR) + ch * 32);
#pragma unroll
        for (int ti = 0; ti < COUNT; ti++) {
            uint32_t b[2];
            ldsm_x2(b, aB + (uint32_t)(start + ti) * (8 * BSTR) + ch * 32);
#pragma unroll
            for (int mi = 0; mi < 2; mi++)
                mma_f16(acc[mi][ti], ah[mi], b);
        }
    }
}

// epilogue: gate exchange via shfl, LSTM cell math, h -> write buffer (fp16)
template<int COUNT>
__device__ __forceinline__ void lstm_epi(float acc[2][7][4], float creg[2][7],
                                         char* sm, uint32_t Aw,
                                         int start, int mtbase, int lane) {
    const int cq = lane & 3;
    const int rq = lane >> 2;
    const bool even = (cq & 1) == 0;
#pragma unroll
    for (int mi = 0; mi < 2; mi++)
#pragma unroll
        for (int ti = 0; ti < COUNT; ti++) {
            float* d = acc[mi][ti];
            float s0 = even ? d[2] : d[0];
            float s1 = even ? d[3] : d[1];
            float e0 = __shfl_xor_sync(0xffffffffu, s0, 1);
            float e1 = __shfl_xor_sync(0xffffffffu, s1, 1);
            float gi, gf, gg, go;
            if (even) { gi = d[0]; gf = d[1]; gg = e0; go = e1; }
            else      { gi = e0;  gf = e1;  gg = d[2]; go = d[3]; }
            float cc = creg[mi][ti];
            cc = sigf(gf) * cc + sigf(gi) * tanha(gg);
            creg[mi][ti] = cc;
            float h = sigf(go) * tanha(cc);
            int row  = (mtbase + mi) * 16 + rq + (even ? 0 : 8);
            int unit = 2 * (start + ti) + (cq >> 1);
            *(uint16_t*)(sm + Aw + row * ASTR + unit * 2) =
                __half_as_ushort(__float2half_rn(h));
        }
}

// ============================ main kernel ============================
__global__ __launch_bounds__(NTHREADS, 1)
void lstm_hmma_kernel(const float* __restrict__ x,
                      const float* __restrict__ Whh1,
                      const float* __restrict__ Wih2,
                      const float* __restrict__ Whh2,
                      const float* __restrict__ bih2,
                      const float* __restrict__ bhh2,
                      const float* __restrict__ W2,
                      const float* __restrict__ b2,
                      float* __restrict__ out) {
    extern __shared__ char sm[];
    const uint32_t smb = sptr(sm);
    const int tid  = threadIdx.x;
    const int warp = tid >> 5;
    const int lane = tid & 31;
    const int b0   = blockIdx.x * MROWS;

    // warp decomposition: 8 N-slices x 2 M-halves
    const int ns     = warp & 7;          // n-slice id
    const int mhalf  = warp >> 3;         // 0 or 1
    const int mtbase = mhalf * 2;         // first m16-tile
    // slices: ns 0,1 -> 7 tiles; ns 2..7 -> 6 tiles (2*7 + 6*6 = 50)
    const int start = (ns < 2) ? ns * 7 : 14 + (ns - 2) * 6;
    const int count = (ns < 2) ? 7 : 6;

    // ldmatrix lane addresses (A base includes the M-half offset)
    const uint32_t aA0 = smb + SM_A + (uint32_t)mtbase * (16 * ASTR)
                       + (uint32_t)(lane & 15) * ASTR + ((lane >> 4) ? 16u : 0u);
    const uint32_t aA1 = aA0 + ABUF;
    const uint32_t aB  = smb + SM_B
                       + (uint32_t)(lane & 7) * BSTR + (((lane >> 3) & 1) ? 16u : 0u);

    // ---- prologue ----
    fill_B(sm, Whh1, g_u1, (const float*)nullptr, g_v1, tid);
    for (int i = tid; i < (2 * ABUF) / 4; i += NTHREADS)
        *(uint32_t*)(sm + SM_A + i * 4) = 0u;
    __syncthreads();
    if (tid < MROWS) {
        // col100 = 1.0 (fp16) in both parity buffers; col101 = x[0] in buffer 0
        *(uint16_t*)(sm + SM_A + tid * ASTR + 200) = 0x3C00u;
        *(uint16_t*)(sm + SM_A + ABUF + tid * ASTR + 200) = 0x3C00u;
        *(uint16_t*)(sm + SM_A + tid * ASTR + 202) =
            __half_as_ushort(__float2half_rn(x[b0 + tid]));
    }
    __syncthreads();

    float creg[2][7];
#pragma unroll
    for (int mi = 0; mi < 2; mi++)
#pragma unroll
        for (int ti = 0; ti < 7; ti++) creg[mi][ti] = 0.f;

    float y[NP];
#pragma unroll
    for (int q = 0; q < NP; q++) y[q] = 0.f;

    // ==================== layer 1: 30 steps, 1 sync/step ====================
#pragma unroll 1
    for (int t = 0; t < T_STEPS; t++) {
        const uint32_t rA   = (t & 1) ? aA1 : aA0;
        const uint32_t wOff = SM_A + (uint32_t)((t + 1) & 1) * ABUF;

        float acc[2][7][4];
#pragma unroll
        for (int mi = 0; mi < 2; mi++)
#pragma unroll
            for (int ti = 0; ti < 7; ti++)
#pragma unroll
                for (int e = 0; e < 4; e++) acc[mi][ti][e] = 0.f;

        if (ns < 2) {
            gemm_step<7>(acc, rA, aB, start);
            lstm_epi<7>(acc, creg, sm, wOff, start, mtbase, lane);
        } else {
            gemm_step<6>(acc, rA, aB, start);
            lstm_epi<6>(acc, creg, sm, wOff, start, mtbase, lane);
        }
        if (tid < MROWS) {
            float xv = (t < T_STEPS - 1) ? x[(t + 1) * BATCH + b0 + tid] : 0.f;
            *(uint16_t*)(sm + wOff + tid * ASTR + 202) =
                __half_as_ushort(__float2half_rn(xv));
        }
        __syncthreads();
    }
    // h_last now in parity buffer 0 (T_STEPS even)

    // ==================== layer-2 input GEMM (once) ====================
    fill_B(sm, Wih2, bih2, bhh2, (const float*)nullptr, tid);
    __syncthreads();
    {
        float acc[2][7][4];
#pragma unroll
        for (int mi = 0; mi < 2; mi++)
#pragma unroll
            for (int ti = 0; ti < 7; ti++)
#pragma unroll
                for (int e = 0; e < 4; e++) acc[mi][ti][e] = 0.f;
        if (ns < 2) gemm_step<7>(acc, aA0, aB, start);
        else        gemm_step<6>(acc, aA0, aB, start);
        float4* slot = &g_in2[((size_t)blockIdx.x * NTHREADS + tid) * 14];
#pragma unroll
        for (int mi = 0; mi < 2; mi++)
            for (int ti = 0; ti < count; ti++)
                slot[mi * 7 + ti] = make_float4(acc[mi][ti][0], acc[mi][ti][1],
                                                acc[mi][ti][2], acc[mi][ti][3]);
    }
    __syncthreads();
    fill_B(sm, Whh2, (const float*)nullptr, (const float*)nullptr,
           (const float*)nullptr, tid);
    __syncthreads();

    // ==================== layer 2: 7 steps + fused FC2 ====================
    const float4* slot = &g_in2[((size_t)blockIdx.x * NTHREADS + tid) * 14];
#pragma unroll 1
    for (int ps = 0; ps < NP; ps++) {
        const uint32_t rA   = (ps & 1) ? aA1 : aA0;
        const uint32_t wOff = SM_A + (uint32_t)((ps + 1) & 1) * ABUF;

        float acc[2][7][4];
#pragma unroll
        for (int mi = 0; mi < 2; mi++)
#pragma unroll
            for (int ti = 0; ti < 7; ti++) {
                float4 v = (ti < count) ? slot[mi * 7 + ti] : make_float4(0.f, 0.f, 0.f, 0.f);
                acc[mi][ti][0] = v.x; acc[mi][ti][1] = v.y;
                acc[mi][ti][2] = v.z; acc[mi][ti][3] = v.w;
            }

        if (ns < 2) {
            gemm_step<7>(acc, rA, aB, start);
            lstm_epi<7>(acc, creg, sm, wOff, start, mtbase, lane);
        } else {
            gemm_step<6>(acc, rA, aB, start);
            lstm_epi<6>(acc, creg, sm, wOff, start, mtbase, lane);
        }
        __syncthreads();

        // stage W2 slice for this ps, then FC2 partial
        float* w2s = (float*)(sm + SM_W2S);
        for (int i = tid; i < 700; i += NTHREADS)
            w2s[i] = W2[(i / 100) * (NP * 100) + ps * 100 + (i % 100)];
        __syncthreads();

        if (tid < 2 * MROWS) {
            int row = tid >> 1;
            int j0  = (tid & 1) * 50;
#pragma unroll 2
            for (int jj = 0; jj < 50; jj++) {
                int j = j0 + jj;
                float h = __half2float(*(const __half*)(sm + wOff + row * ASTR + j * 2));
#pragma unroll
                for (int q = 0; q < NP; q++)
                    y[q] = fmaf(h, w2s[q * 100 + j], y[q]);
            }
        }
    }

    // ==================== output ====================
    if (tid < 2 * MROWS) {
        int row = tid >> 1;
#pragma unroll
        for (int q = 0; q < NP; q++) {
            float v = y[q] + __shfl_xor_sync(0xffffffffu, y[q], 1);
            if ((tid & 1) == 0)
                out[(size_t)(b0 + row) * NP + q] = sigf(v + b2[q]);
        }
    }
}

// ============================ launch ============================
extern "C" void kernel_launch(void* const* d_in, const int* in_sizes, int n_in,
                              void* d_out, int out_size) {
    const float* x    = (const float*)d_in[0];
    const float* W1   = (const float*)d_in[1];
    const float* b1   = (const float*)d_in[2];
    const float* Wih1 = (const float*)d_in[3];
    const float* Whh1 = (const float*)d_in[4];
    const float* bih1 = (const float*)d_in[5];
    const float* bhh1 = (const float*)d_in[6];
    const float* Wih2 = (const float*)d_in[7];
    const float* Whh2 = (const float*)d_in[8];
    const float* bih2 = (const float*)d_in[9];
    const float* bhh2 = (const float*)d_in[10];
    const float* W2   = (const float*)d_in[11];
    const float* b2   = (const float*)d_in[12];
    float* out = (float*)d_out;

    cudaFuncSetAttribute(lstm_hmma_kernel,
                         cudaFuncAttributeMaxDynamicSharedMemorySize, SMEM_BYTES);

    precompute_kernel<<<1, 512>>>(W1, b1, Wih1, bih1, bhh1);
    lstm_hmma_kernel<<<NCTAS, NTHREADS, SMEM_BYTES>>>(
        x, Whh1, Wih2, Whh2, bih2, bhh2, W2, b2, out);
}